// round 2
// baseline (speedup 1.0000x reference)
#include <cuda_runtime.h>
#include <cstdint>
#include <cstddef>

#define VN 16384
#define CN 16
#define LN 6
#define DN 64
#define TROWS (2 * VN + 1)   // 32769: [0,V)=plain, [V,2V)=negated, 2V=false_emb

// ---------------- device scratch (static: no runtime allocation allowed) ----------------
__device__ float g_negT[(VN + 1) * DN];            // rows 0..V-1: vars@Wn+bn ; row V: true_emb
__device__ float g_P[LN * TROWS * 128];            // per-l table @ [W1v_l | W2v_l]  (~100.7MB)
__device__ float g_ce[(size_t)VN * CN * DN];       // clause embeddings (67MB)
__device__ float g_y[(size_t)VN * 128];            // clause-combiner pre-activation
__device__ float g_Wc[1024 * 128];                 // [W1c | W2c] concatenated
__device__ int   g_flags[3];
__device__ int   g_mode;                           // 0: 4-byte word, 1: u8, 2: 16-bit

// ---------------- helpers ----------------
__device__ __forceinline__ bool read_mask(const void* p, size_t i, int mode) {
    if (mode == 1) return ((const unsigned char*)p)[i] != 0;
    if (mode == 2) return ((const unsigned short*)p)[i] != 0;
    return ((const unsigned int*)p)[i] != 0;   // int32 or float32: nonzero == true
}
__device__ __forceinline__ float sigf(float x) { return 1.f / (1.f + __expf(-x)); }

// ---------------- K0: detect boolean encoding ----------------
__global__ void k_reset() { g_flags[0] = 0; g_flags[1] = 0; g_flags[2] = 0; }

__global__ void k_scan(const unsigned int* __restrict__ w, int nwords) {
    int i = blockIdx.x * blockDim.x + threadIdx.x;
    int bad4 = 0, bad1 = 0, bad2 = 0;
    for (; i < nwords; i += gridDim.x * blockDim.x) {
        unsigned int x = w[i];
        if (!(x == 0u || x == 1u || x == 0x3F800000u)) bad4 = 1;
        if (x & 0xFEFEFEFEu) bad1 = 1;
        unsigned int h0 = x & 0xFFFFu, h1 = x >> 16;
        bool ok0 = (h0 == 0u || h0 == 0x3F80u || h0 == 0x3C00u);
        bool ok1 = (h1 == 0u || h1 == 0x3F80u || h1 == 0x3C00u);
        if (!(ok0 && ok1)) bad2 = 1;
    }
    const unsigned FULL = 0xffffffffu;
    int lane = threadIdx.x & 31;
    bad4 = __any_sync(FULL, bad4);
    bad1 = __any_sync(FULL, bad1);
    bad2 = __any_sync(FULL, bad2);
    if (lane == 0) {
        if (bad4) atomicOr(&g_flags[0], 1);
        if (bad1) atomicOr(&g_flags[1], 1);
        if (bad2) atomicOr(&g_flags[2], 1);
    }
}

__global__ void k_mode() {
    g_mode = (g_flags[0] == 0) ? 0 : ((g_flags[1] == 0) ? 1 : 2);
}

// ---------------- K1a: negT = [variables; false_emb] @ Wn + bn ----------------
__global__ __launch_bounds__(256) void k_neg(const float* __restrict__ vars,
                                             const float* __restrict__ false_emb,
                                             const float* __restrict__ Wn,
                                             const float* __restrict__ bn) {
    __shared__ float Wn_s[64][64];
    __shared__ float src_s[4][64];
    const int tid = threadIdx.x;
    #pragma unroll
    for (int t = 0; t < 4; ++t) {
        int f4 = tid + 256 * t;
        int k = f4 >> 4, q = f4 & 15;
        *(float4*)&Wn_s[k][q * 4] = *(const float4*)(Wn + k * 64 + q * 4);
    }
    {
        int r = tid >> 6, k = tid & 63;
        int row = blockIdx.x * 4 + r;
        float v = 0.f;
        if (row < VN) v = vars[(size_t)row * 64 + k];
        else if (row == VN) v = false_emb[k];
        src_s[r][k] = v;
    }
    __syncthreads();
    const int rt = tid >> 6, d = tid & 63;
    const int row = blockIdx.x * 4 + rt;
    float acc = bn[d];
    #pragma unroll 16
    for (int k = 0; k < 64; ++k) acc += src_s[rt][k] * Wn_s[k][d];
    if (row <= VN) g_negT[(size_t)row * 64 + d] = acc;
}

// ---------------- K1b: P_l = T @ [W1v_l | W2v_l] ----------------
__global__ __launch_bounds__(256) void k_build_P(const float* __restrict__ vars,
                                                 const float* __restrict__ false_emb,
                                                 const float* __restrict__ W1v,
                                                 const float* __restrict__ W2v) {
    __shared__ float T_s[64][64];     // 16KB
    __shared__ float W_s[64][128];    // 32KB
    const int tid = threadIdx.x;
    const int l = blockIdx.y;
    const int r0 = blockIdx.x * 64;

    #pragma unroll
    for (int t = 0; t < 8; ++t) {
        int f4 = tid + 256 * t;
        int k = f4 >> 5, cq = f4 & 31;
        const float* src = (cq < 16)
            ? (W1v + ((size_t)(l * 64 + k)) * 64 + cq * 4)
            : (W2v + ((size_t)(l * 64 + k)) * 64 + (cq - 16) * 4);
        *(float4*)&W_s[k][cq * 4] = *(const float4*)src;
    }
    // FIX: T_s is 64 rows x 16 float4s = 1024 float4s -> need t < 4 (was t < 2,
    // leaving rows 32..63 uninitialized -> rel_err 0.16)
    #pragma unroll
    for (int t = 0; t < 4; ++t) {
        int f4 = tid + 256 * t;
        int r = f4 >> 4, kq = f4 & 15;
        int rr = r0 + r;
        float4 v = make_float4(0.f, 0.f, 0.f, 0.f);
        if (rr < VN)           v = *(const float4*)(vars + (size_t)rr * 64 + kq * 4);
        else if (rr < 2 * VN)  v = *(const float4*)(g_negT + (size_t)(rr - VN) * 64 + kq * 4);
        else if (rr == 2 * VN) v = *(const float4*)(false_emb + kq * 4);
        *(float4*)&T_s[r][kq * 4] = v;
    }
    __syncthreads();

    const int rgi = tid >> 4, cgi = tid & 15;
    float acc[4][8];
    #pragma unroll
    for (int i = 0; i < 4; ++i)
        #pragma unroll
        for (int j = 0; j < 8; ++j) acc[i][j] = 0.f;

    #pragma unroll 8
    for (int k = 0; k < 64; ++k) {
        float a[4];
        #pragma unroll
        for (int i = 0; i < 4; ++i) a[i] = T_s[rgi * 4 + i][k];
        float4 b0 = *(const float4*)&W_s[k][cgi * 8];
        float4 b1 = *(const float4*)&W_s[k][cgi * 8 + 4];
        float b[8] = {b0.x, b0.y, b0.z, b0.w, b1.x, b1.y, b1.z, b1.w};
        #pragma unroll
        for (int i = 0; i < 4; ++i)
            #pragma unroll
            for (int j = 0; j < 8; ++j) acc[i][j] += a[i] * b[j];
    }

    #pragma unroll
    for (int i = 0; i < 4; ++i) {
        int rr = r0 + rgi * 4 + i;
        if (rr < TROWS) {
            float* dst = g_P + ((size_t)l * TROWS + rr) * 128 + cgi * 8;
            *(float4*)dst       = make_float4(acc[i][0], acc[i][1], acc[i][2], acc[i][3]);
            *(float4*)(dst + 4) = make_float4(acc[i][4], acc[i][5], acc[i][6], acc[i][7]);
        }
    }
}

// ---------------- Kw: concat W1c|W2c ----------------
__global__ void k_wc(const float* __restrict__ W1c, const float* __restrict__ W2c) {
    int i = blockIdx.x * blockDim.x + threadIdx.x;
    if (i < 1024 * 128) {
        int k = i >> 7, j = i & 127;
        g_Wc[i] = (j < 64) ? W1c[k * 64 + j] : W2c[k * 64 + (j - 64)];
    }
}

// ---------------- K2: clause embeddings (one warp per (v,c)) ----------------
__global__ __launch_bounds__(256) void k_clause(const int* __restrict__ lits,
                                                const void* __restrict__ negm,
                                                const void* __restrict__ vvalid,
                                                const void* __restrict__ cvalid,
                                                const float* __restrict__ b1v,
                                                const float* __restrict__ b2v) {
    const unsigned FULL = 0xffffffffu;
    const int gw = (blockIdx.x * blockDim.x + threadIdx.x) >> 5;
    const int lane = threadIdx.x & 31;
    if (gw >= VN * CN) return;
    const int mode = g_mode;

    int rowid = 2 * VN;
    if (lane < LN) {
        size_t base = (size_t)gw * LN + lane;
        int idx = lits[base];
        bool neg = read_mask(negm, base, mode);
        bool val = read_mask(vvalid, base, mode);
        rowid = val ? (neg ? idx + VN : idx) : 2 * VN;
    }

    const float* bp = (lane < 16) ? (b1v + lane * 4) : (b2v + (lane - 16) * 4);
    float4 acc = *(const float4*)bp;
    #pragma unroll
    for (int l = 0; l < LN; ++l) {
        int r = __shfl_sync(FULL, rowid, l);
        float4 t = __ldg((const float4*)(g_P + ((size_t)l * TROWS + r) * 128) + lane);
        acc.x += t.x; acc.y += t.y; acc.z += t.z; acc.w += t.w;
    }

    float4 lin;
    lin.x = __shfl_down_sync(FULL, acc.x, 16);
    lin.y = __shfl_down_sync(FULL, acc.y, 16);
    lin.z = __shfl_down_sync(FULL, acc.z, 16);
    lin.w = __shfl_down_sync(FULL, acc.w, 16);

    float hx = 0.f, hy = 0.f, hz = 0.f, hw = 0.f, ss = 0.f;
    if (lane < 16) {
        hx = sigf(acc.x) + lin.x;
        hy = sigf(acc.y) + lin.y;
        hz = sigf(acc.z) + lin.z;
        hw = sigf(acc.w) + lin.w;
        ss = hx * hx + hy * hy + hz * hz + hw * hw;
    }
    #pragma unroll
    for (int o = 16; o; o >>= 1) ss += __shfl_xor_sync(FULL, ss, o);
    float inv = rsqrtf(ss);

    bool cv = read_mask(cvalid, (size_t)gw, mode);
    if (lane < 16) {
        float4 o4;
        if (cv) {
            o4 = make_float4(hx * inv, hy * inv, hz * inv, hw * inv);
        } else {
            o4 = *(const float4*)(g_negT + (size_t)VN * 64 + lane * 4);  // true_emb
        }
        *(float4*)(g_ce + (size_t)gw * 64 + lane * 4) = o4;
    }
}

// ---------------- K3: [V,1024] @ [1024,128] -> g_y ----------------
__global__ __launch_bounds__(256) void k_gemm() {
    __shared__ float A_s[64][32];    // 8KB
    __shared__ float B_s[32][128];   // 16KB
    const int tid = threadIdx.x;
    const int r0 = blockIdx.x * 64;
    const int rgi = tid >> 4, cgi = tid & 15;

    float acc[4][8];
    #pragma unroll
    for (int i = 0; i < 4; ++i)
        #pragma unroll
        for (int j = 0; j < 8; ++j) acc[i][j] = 0.f;

    for (int kc = 0; kc < 1024; kc += 32) {
        #pragma unroll
        for (int t = 0; t < 2; ++t) {
            int f4 = tid + 256 * t;
            int r = f4 >> 3, kq = f4 & 7;
            *(float4*)&A_s[r][kq * 4] =
                *(const float4*)(g_ce + (size_t)(r0 + r) * 1024 + kc + kq * 4);
        }
        #pragma unroll
        for (int t = 0; t < 4; ++t) {
            int f4 = tid + 256 * t;
            int k = f4 >> 5, cq = f4 & 31;
            *(float4*)&B_s[k][cq * 4] =
                *(const float4*)(g_Wc + (size_t)(kc + k) * 128 + cq * 4);
        }
        __syncthreads();
        #pragma unroll 8
        for (int k = 0; k < 32; ++k) {
            float a[4];
            #pragma unroll
            for (int i = 0; i < 4; ++i) a[i] = A_s[rgi * 4 + i][k];
            float4 b0 = *(const float4*)&B_s[k][cgi * 8];
            float4 b1 = *(const float4*)&B_s[k][cgi * 8 + 4];
            float b[8] = {b0.x, b0.y, b0.z, b0.w, b1.x, b1.y, b1.z, b1.w};
            #pragma unroll
            for (int i = 0; i < 4; ++i)
                #pragma unroll
                for (int j = 0; j < 8; ++j) acc[i][j] += a[i] * b[j];
        }
        __syncthreads();
    }

    #pragma unroll
    for (int i = 0; i < 4; ++i) {
        int r = r0 + rgi * 4 + i;
        float* dst = g_y + (size_t)r * 128 + cgi * 8;
        *(float4*)dst       = make_float4(acc[i][0], acc[i][1], acc[i][2], acc[i][3]);
        *(float4*)(dst + 4) = make_float4(acc[i][4], acc[i][5], acc[i][6], acc[i][7]);
    }
}

// ---------------- K4: final combine + normalize + passthrough ----------------
__global__ __launch_bounds__(256) void k_final(const float* __restrict__ vars,
                                               const void* __restrict__ cvalid,
                                               const float* __restrict__ b1c,
                                               const float* __restrict__ b2c,
                                               float* __restrict__ out) {
    const unsigned FULL = 0xffffffffu;
    const int gw = (blockIdx.x * blockDim.x + threadIdx.x) >> 5;  // variable index
    const int lane = threadIdx.x & 31;
    if (gw >= VN) return;
    const int mode = g_mode;

    const float* bp = (lane < 16) ? (b1c + lane * 4) : (b2c + (lane - 16) * 4);
    float4 acc = *(const float4*)bp;
    float4 yv = *(const float4*)(g_y + (size_t)gw * 128 + lane * 4);
    acc.x += yv.x; acc.y += yv.y; acc.z += yv.z; acc.w += yv.w;

    float4 lin;
    lin.x = __shfl_down_sync(FULL, acc.x, 16);
    lin.y = __shfl_down_sync(FULL, acc.y, 16);
    lin.z = __shfl_down_sync(FULL, acc.z, 16);
    lin.w = __shfl_down_sync(FULL, acc.w, 16);

    float hx = 0.f, hy = 0.f, hz = 0.f, hw = 0.f, ss = 0.f;
    if (lane < 16) {
        hx = sigf(acc.x) + lin.x;
        hy = sigf(acc.y) + lin.y;
        hz = sigf(acc.z) + lin.z;
        hw = sigf(acc.w) + lin.w;
        ss = hx * hx + hy * hy + hz * hz + hw * hw;
    }
    #pragma unroll
    for (int o = 16; o; o >>= 1) ss += __shfl_xor_sync(FULL, ss, o);
    float inv = rsqrtf(ss);

    bool cv = (lane < 16) ? read_mask(cvalid, (size_t)gw * CN + lane, mode) : false;
    bool has = __ballot_sync(FULL, cv) != 0u;

    if (lane < 16) {
        float4 o4;
        if (has) {
            o4 = make_float4(hx * inv, hy * inv, hz * inv, hw * inv);
        } else {
            o4 = *(const float4*)(vars + (size_t)gw * 64 + lane * 4);
        }
        *(float4*)(out + (size_t)gw * 64 + lane * 4) = o4;
    }
}

// ---------------- launch ----------------
extern "C" void kernel_launch(void* const* d_in, const int* in_sizes, int n_in,
                              void* d_out, int out_size) {
    const float* vars      = (const float*)d_in[0];
    const int*   lits      = (const int*)d_in[1];
    const void*  negm      = d_in[2];
    const void*  vval      = d_in[3];
    const void*  cval      = d_in[4];
    const float* Wn        = (const float*)d_in[5];
    const float* bn        = (const float*)d_in[6];
    const float* false_emb = (const float*)d_in[7];
    const float* W1v       = (const float*)d_in[8];
    const float* b1v       = (const float*)d_in[9];
    const float* W2v       = (const float*)d_in[10];
    const float* b2v       = (const float*)d_in[11];
    const float* W1c       = (const float*)d_in[12];
    const float* b1c       = (const float*)d_in[13];
    const float* W2c       = (const float*)d_in[14];
    const float* b2c       = (const float*)d_in[15];
    float* out = (float*)d_out;

    // K0: boolean encoding detection (deterministic, data-driven)
    k_reset<<<1, 1>>>();
    const int nwords = (VN * CN * LN) / 4;
    k_scan<<<1024, 256>>>((const unsigned int*)negm, nwords);
    k_mode<<<1, 1>>>();

    // K1: precompute negation table + per-slot projected tables + concat Wc
    k_neg<<<(VN + 1 + 3) / 4, 256>>>(vars, false_emb, Wn, bn);
    k_build_P<<<dim3((TROWS + 63) / 64, LN), 256>>>(vars, false_emb, W1v, W2v);
    k_wc<<<(1024 * 128 + 255) / 256, 256>>>(W1c, W2c);

    // K2: clause embeddings via gather-and-add of projected tables
    k_clause<<<(VN * CN) / 8, 256>>>(lits, negm, vval, cval, b1v, b2v);

    // K3: clause combiner GEMM
    k_gemm<<<VN / 64, 256>>>();

    // K4: final residual combine + normalize + no-clause passthrough
    k_final<<<VN / 8, 256>>>(vars, cval, b1c, b2c, out);
}

// round 3
// speedup vs baseline: 1.1597x; 1.1597x over previous
#include <cuda_runtime.h>
#include <cuda_fp16.h>
#include <cstdint>
#include <cstddef>

#define VN 16384
#define CN 16
#define LN 6
#define DN 64
#define TROWS (2 * VN + 1)   // 32769: [0,V)=plain, [V,2V)=negated, 2V=false_emb

// ---------------- device scratch (static: no runtime allocation allowed) ----------------
__device__ float  g_negT[(VN + 1) * DN];           // rows 0..V-1: vars@Wn+bn ; row V: true_emb
__device__ __half g_P[(size_t)LN * TROWS * 128];   // per-l table @ [W1v_l | W2v_l]  (~50.3MB, fp16)
__device__ float  g_ce[(size_t)VN * CN * DN];      // clause embeddings (67MB)
__device__ float  g_y[(size_t)VN * 128];           // clause-combiner pre-activation
__device__ float  g_Wc[1024 * 128];                // [W1c | W2c] concatenated
__device__ int    g_flags[3];
__device__ int    g_mode;                          // 0: 4-byte word, 1: u8, 2: 16-bit

// ---------------- helpers ----------------
__device__ __forceinline__ bool read_mask(const void* p, size_t i, int mode) {
    if (mode == 1) return ((const unsigned char*)p)[i] != 0;
    if (mode == 2) return ((const unsigned short*)p)[i] != 0;
    return ((const unsigned int*)p)[i] != 0;   // int32 or float32: nonzero == true
}
__device__ __forceinline__ float sigf(float x) { return 1.f / (1.f + __expf(-x)); }

// ---------------- K0: detect boolean encoding ----------------
__global__ void k_reset() { g_flags[0] = 0; g_flags[1] = 0; g_flags[2] = 0; }

__global__ void k_scan(const unsigned int* __restrict__ w, int nwords) {
    int i = blockIdx.x * blockDim.x + threadIdx.x;
    int bad4 = 0, bad1 = 0, bad2 = 0;
    for (; i < nwords; i += gridDim.x * blockDim.x) {
        unsigned int x = w[i];
        if (!(x == 0u || x == 1u || x == 0x3F800000u)) bad4 = 1;
        if (x & 0xFEFEFEFEu) bad1 = 1;
        unsigned int h0 = x & 0xFFFFu, h1 = x >> 16;
        bool ok0 = (h0 == 0u || h0 == 0x3F80u || h0 == 0x3C00u);
        bool ok1 = (h1 == 0u || h1 == 0x3F80u || h1 == 0x3C00u);
        if (!(ok0 && ok1)) bad2 = 1;
    }
    const unsigned FULL = 0xffffffffu;
    int lane = threadIdx.x & 31;
    bad4 = __any_sync(FULL, bad4);
    bad1 = __any_sync(FULL, bad1);
    bad2 = __any_sync(FULL, bad2);
    if (lane == 0) {
        if (bad4) atomicOr(&g_flags[0], 1);
        if (bad1) atomicOr(&g_flags[1], 1);
        if (bad2) atomicOr(&g_flags[2], 1);
    }
}

__global__ void k_mode() {
    g_mode = (g_flags[0] == 0) ? 0 : ((g_flags[1] == 0) ? 1 : 2);
}

// ---------------- K1a: negT = [variables; false_emb] @ Wn + bn  (16 rows/block) ----------------
__global__ __launch_bounds__(256) void k_neg(const float* __restrict__ vars,
                                             const float* __restrict__ false_emb,
                                             const float* __restrict__ Wn,
                                             const float* __restrict__ bn) {
    __shared__ float Wn_s[64][64];
    __shared__ float src_s[16][64];
    const int tid = threadIdx.x;
    #pragma unroll
    for (int t = 0; t < 4; ++t) {
        int f4 = tid + 256 * t;
        int k = f4 >> 4, q = f4 & 15;
        *(float4*)&Wn_s[k][q * 4] = *(const float4*)(Wn + k * 64 + q * 4);
    }
    {
        int r = tid >> 4, kq = tid & 15;
        int row = blockIdx.x * 16 + r;
        float4 v = make_float4(0.f, 0.f, 0.f, 0.f);
        if (row < VN)       v = *(const float4*)(vars + (size_t)row * 64 + kq * 4);
        else if (row == VN) v = *(const float4*)(false_emb + kq * 4);
        *(float4*)&src_s[r][kq * 4] = v;
    }
    __syncthreads();
    const int rt = tid >> 6, d = tid & 63;
    const float bd = bn[d];
    #pragma unroll
    for (int t = 0; t < 4; ++t) {
        int rl = rt * 4 + t;
        int row = blockIdx.x * 16 + rl;
        float acc = bd;
        #pragma unroll 16
        for (int k = 0; k < 64; ++k) acc += src_s[rl][k] * Wn_s[k][d];
        if (row <= VN) g_negT[(size_t)row * 64 + d] = acc;
    }
}

// ---------------- K1b: P_l = T @ [W1v_l | W2v_l]  -> fp16 ----------------
__global__ __launch_bounds__(256) void k_build_P(const float* __restrict__ vars,
                                                 const float* __restrict__ false_emb,
                                                 const float* __restrict__ W1v,
                                                 const float* __restrict__ W2v) {
    __shared__ float T_s[64][64];     // 16KB
    __shared__ float W_s[64][128];    // 32KB
    const int tid = threadIdx.x;
    const int l = blockIdx.y;
    const int r0 = blockIdx.x * 64;

    #pragma unroll
    for (int t = 0; t < 8; ++t) {
        int f4 = tid + 256 * t;
        int k = f4 >> 5, cq = f4 & 31;
        const float* src = (cq < 16)
            ? (W1v + ((size_t)(l * 64 + k)) * 64 + cq * 4)
            : (W2v + ((size_t)(l * 64 + k)) * 64 + (cq - 16) * 4);
        *(float4*)&W_s[k][cq * 4] = *(const float4*)src;
    }
    #pragma unroll
    for (int t = 0; t < 4; ++t) {
        int f4 = tid + 256 * t;
        int r = f4 >> 4, kq = f4 & 15;
        int rr = r0 + r;
        float4 v = make_float4(0.f, 0.f, 0.f, 0.f);
        if (rr < VN)           v = *(const float4*)(vars + (size_t)rr * 64 + kq * 4);
        else if (rr < 2 * VN)  v = *(const float4*)(g_negT + (size_t)(rr - VN) * 64 + kq * 4);
        else if (rr == 2 * VN) v = *(const float4*)(false_emb + kq * 4);
        *(float4*)&T_s[r][kq * 4] = v;
    }
    __syncthreads();

    const int rgi = tid >> 4, cgi = tid & 15;
    float acc[4][8];
    #pragma unroll
    for (int i = 0; i < 4; ++i)
        #pragma unroll
        for (int j = 0; j < 8; ++j) acc[i][j] = 0.f;

    #pragma unroll 8
    for (int k = 0; k < 64; ++k) {
        float a[4];
        #pragma unroll
        for (int i = 0; i < 4; ++i) a[i] = T_s[rgi * 4 + i][k];
        float4 b0 = *(const float4*)&W_s[k][cgi * 8];
        float4 b1 = *(const float4*)&W_s[k][cgi * 8 + 4];
        float b[8] = {b0.x, b0.y, b0.z, b0.w, b1.x, b1.y, b1.z, b1.w};
        #pragma unroll
        for (int i = 0; i < 4; ++i)
            #pragma unroll
            for (int j = 0; j < 8; ++j) acc[i][j] += a[i] * b[j];
    }

    #pragma unroll
    for (int i = 0; i < 4; ++i) {
        int rr = r0 + rgi * 4 + i;
        if (rr < TROWS) {
            __half2 h0 = __floats2half2_rn(acc[i][0], acc[i][1]);
            __half2 h1 = __floats2half2_rn(acc[i][2], acc[i][3]);
            __half2 h2 = __floats2half2_rn(acc[i][4], acc[i][5]);
            __half2 h3 = __floats2half2_rn(acc[i][6], acc[i][7]);
            uint4 pk;
            pk.x = *(unsigned int*)&h0; pk.y = *(unsigned int*)&h1;
            pk.z = *(unsigned int*)&h2; pk.w = *(unsigned int*)&h3;
            *(uint4*)(g_P + ((size_t)l * TROWS + rr) * 128 + cgi * 8) = pk;
        }
    }
}

// ---------------- Kw: concat W1c|W2c ----------------
__global__ void k_wc(const float* __restrict__ W1c, const float* __restrict__ W2c) {
    int i = blockIdx.x * blockDim.x + threadIdx.x;
    if (i < 1024 * 128) {
        int k = i >> 7, j = i & 127;
        g_Wc[i] = (j < 64) ? W1c[k * 64 + j] : W2c[k * 64 + (j - 64)];
    }
}

// ---------------- K2: clause embeddings (one warp per (v,c)), fp16 gathers ----------------
__global__ __launch_bounds__(256) void k_clause(const int* __restrict__ lits,
                                                const void* __restrict__ negm,
                                                const void* __restrict__ vvalid,
                                                const void* __restrict__ cvalid,
                                                const float* __restrict__ b1v,
                                                const float* __restrict__ b2v) {
    const unsigned FULL = 0xffffffffu;
    const int gw = (blockIdx.x * blockDim.x + threadIdx.x) >> 5;
    const int lane = threadIdx.x & 31;
    if (gw >= VN * CN) return;
    const int mode = g_mode;

    int rowid = 2 * VN;
    if (lane < LN) {
        size_t base = (size_t)gw * LN + lane;
        int idx = lits[base];
        bool neg = read_mask(negm, base, mode);
        bool val = read_mask(vvalid, base, mode);
        rowid = val ? (neg ? idx + VN : idx) : 2 * VN;
    }

    const float* bp = (lane < 16) ? (b1v + lane * 4) : (b2v + (lane - 16) * 4);
    float4 acc = *(const float4*)bp;
    #pragma unroll
    for (int l = 0; l < LN; ++l) {
        int r = __shfl_sync(FULL, rowid, l);
        uint2 u = __ldg((const uint2*)(g_P + ((size_t)l * TROWS + r) * 128) + lane);
        __half2 h0 = *(__half2*)&u.x;
        __half2 h1 = *(__half2*)&u.y;
        float2 f0 = __half22float2(h0);
        float2 f1 = __half22float2(h1);
        acc.x += f0.x; acc.y += f0.y; acc.z += f1.x; acc.w += f1.y;
    }

    float4 lin;
    lin.x = __shfl_down_sync(FULL, acc.x, 16);
    lin.y = __shfl_down_sync(FULL, acc.y, 16);
    lin.z = __shfl_down_sync(FULL, acc.z, 16);
    lin.w = __shfl_down_sync(FULL, acc.w, 16);

    float hx = 0.f, hy = 0.f, hz = 0.f, hw = 0.f, ss = 0.f;
    if (lane < 16) {
        hx = sigf(acc.x) + lin.x;
        hy = sigf(acc.y) + lin.y;
        hz = sigf(acc.z) + lin.z;
        hw = sigf(acc.w) + lin.w;
        ss = hx * hx + hy * hy + hz * hz + hw * hw;
    }
    #pragma unroll
    for (int o = 16; o; o >>= 1) ss += __shfl_xor_sync(FULL, ss, o);
    float inv = rsqrtf(ss);

    bool cv = read_mask(cvalid, (size_t)gw, mode);
    if (lane < 16) {
        float4 o4;
        if (cv) {
            o4 = make_float4(hx * inv, hy * inv, hz * inv, hw * inv);
        } else {
            o4 = *(const float4*)(g_negT + (size_t)VN * 64 + lane * 4);  // true_emb
        }
        *(float4*)(g_ce + (size_t)gw * 64 + lane * 4) = o4;
    }
}

// ---------------- K3: [V,1024] @ [1024,128] -> g_y  (128x128 tiles) ----------------
__global__ __launch_bounds__(256) void k_gemm() {
    __shared__ float A_s[128][32];   // 16KB
    __shared__ float B_s[32][128];   // 16KB
    const int tid = threadIdx.x;
    const int r0 = blockIdx.x * 128;
    const int rgi = tid >> 4, cgi = tid & 15;

    float acc[8][8];
    #pragma unroll
    for (int i = 0; i < 8; ++i)
        #pragma unroll
        for (int j = 0; j < 8; ++j) acc[i][j] = 0.f;

    for (int kc = 0; kc < 1024; kc += 32) {
        #pragma unroll
        for (int t = 0; t < 4; ++t) {
            int f4 = tid + 256 * t;
            int r = f4 >> 3, kq = f4 & 7;
            *(float4*)&A_s[r][kq * 4] =
                *(const float4*)(g_ce + (size_t)(r0 + r) * 1024 + kc + kq * 4);
        }
        #pragma unroll
        for (int t = 0; t < 4; ++t) {
            int f4 = tid + 256 * t;
            int k = f4 >> 5, cq = f4 & 31;
            *(float4*)&B_s[k][cq * 4] =
                *(const float4*)(g_Wc + (size_t)(kc + k) * 128 + cq * 4);
        }
        __syncthreads();
        #pragma unroll 8
        for (int k = 0; k < 32; ++k) {
            float a[8];
            #pragma unroll
            for (int i = 0; i < 8; ++i) a[i] = A_s[rgi * 8 + i][k];
            float4 b0 = *(const float4*)&B_s[k][cgi * 8];
            float4 b1 = *(const float4*)&B_s[k][cgi * 8 + 4];
            float b[8] = {b0.x, b0.y, b0.z, b0.w, b1.x, b1.y, b1.z, b1.w};
            #pragma unroll
            for (int i = 0; i < 8; ++i)
                #pragma unroll
                for (int j = 0; j < 8; ++j) acc[i][j] += a[i] * b[j];
        }
        __syncthreads();
    }

    #pragma unroll
    for (int i = 0; i < 8; ++i) {
        int r = r0 + rgi * 8 + i;
        float* dst = g_y + (size_t)r * 128 + cgi * 8;
        *(float4*)dst       = make_float4(acc[i][0], acc[i][1], acc[i][2], acc[i][3]);
        *(float4*)(dst + 4) = make_float4(acc[i][4], acc[i][5], acc[i][6], acc[i][7]);
    }
}

// ---------------- K4: final combine + normalize + passthrough ----------------
__global__ __launch_bounds__(256) void k_final(const float* __restrict__ vars,
                                               const void* __restrict__ cvalid,
                                               const float* __restrict__ b1c,
                                               const float* __restrict__ b2c,
                                               float* __restrict__ out) {
    const unsigned FULL = 0xffffffffu;
    const int gw = (blockIdx.x * blockDim.x + threadIdx.x) >> 5;  // variable index
    const int lane = threadIdx.x & 31;
    if (gw >= VN) return;
    const int mode = g_mode;

    const float* bp = (lane < 16) ? (b1c + lane * 4) : (b2c + (lane - 16) * 4);
    float4 acc = *(const float4*)bp;
    float4 yv = *(const float4*)(g_y + (size_t)gw * 128 + lane * 4);
    acc.x += yv.x; acc.y += yv.y; acc.z += yv.z; acc.w += yv.w;

    float4 lin;
    lin.x = __shfl_down_sync(FULL, acc.x, 16);
    lin.y = __shfl_down_sync(FULL, acc.y, 16);
    lin.z = __shfl_down_sync(FULL, acc.z, 16);
    lin.w = __shfl_down_sync(FULL, acc.w, 16);

    float hx = 0.f, hy = 0.f, hz = 0.f, hw = 0.f, ss = 0.f;
    if (lane < 16) {
        hx = sigf(acc.x) + lin.x;
        hy = sigf(acc.y) + lin.y;
        hz = sigf(acc.z) + lin.z;
        hw = sigf(acc.w) + lin.w;
        ss = hx * hx + hy * hy + hz * hz + hw * hw;
    }
    #pragma unroll
    for (int o = 16; o; o >>= 1) ss += __shfl_xor_sync(FULL, ss, o);
    float inv = rsqrtf(ss);

    bool cv = (lane < 16) ? read_mask(cvalid, (size_t)gw * CN + lane, mode) : false;
    bool has = __ballot_sync(FULL, cv) != 0u;

    if (lane < 16) {
        float4 o4;
        if (has) {
            o4 = make_float4(hx * inv, hy * inv, hz * inv, hw * inv);
        } else {
            o4 = *(const float4*)(vars + (size_t)gw * 64 + lane * 4);
        }
        *(float4*)(out + (size_t)gw * 64 + lane * 4) = o4;
    }
}

// ---------------- launch ----------------
extern "C" void kernel_launch(void* const* d_in, const int* in_sizes, int n_in,
                              void* d_out, int out_size) {
    const float* vars      = (const float*)d_in[0];
    const int*   lits      = (const int*)d_in[1];
    const void*  negm      = d_in[2];
    const void*  vval      = d_in[3];
    const void*  cval      = d_in[4];
    const float* Wn        = (const float*)d_in[5];
    const float* bn        = (const float*)d_in[6];
    const float* false_emb = (const float*)d_in[7];
    const float* W1v       = (const float*)d_in[8];
    const float* b1v       = (const float*)d_in[9];
    const float* W2v       = (const float*)d_in[10];
    const float* b2v       = (const float*)d_in[11];
    const float* W1c       = (const float*)d_in[12];
    const float* b1c       = (const float*)d_in[13];
    const float* W2c       = (const float*)d_in[14];
    const float* b2c       = (const float*)d_in[15];
    float* out = (float*)d_out;

    // K0: boolean encoding detection (deterministic, data-driven)
    k_reset<<<1, 1>>>();
    const int nwords = (VN * CN * LN) / 4;
    k_scan<<<1024, 256>>>((const unsigned int*)negm, nwords);
    k_mode<<<1, 1>>>();

    // K1: precompute negation table + per-slot projected tables (fp16) + concat Wc
    k_neg<<<(VN + 1 + 15) / 16, 256>>>(vars, false_emb, Wn, bn);
    k_build_P<<<dim3((TROWS + 63) / 64, LN), 256>>>(vars, false_emb, W1v, W2v);
    k_wc<<<(1024 * 128 + 255) / 256, 256>>>(W1c, W2c);

    // K2: clause embeddings via fp16 gather-and-add of projected tables
    k_clause<<<(VN * CN) / 8, 256>>>(lits, negm, vval, cval, b1v, b2v);

    // K3: clause combiner GEMM (128x128 tiles)
    k_gemm<<<VN / 128, 256>>>();

    // K4: final residual combine + normalize + no-clause passthrough
    k_final<<<VN / 8, 256>>>(vars, cval, b1c, b2c, out);
}

// round 4
// speedup vs baseline: 1.2681x; 1.0935x over previous
#include <cuda_runtime.h>
#include <cuda_fp16.h>
#include <cstdint>
#include <cstddef>

#define VN 16384
#define CN 16
#define LN 6
#define DN 64
#define TROWS (2 * VN + 1)   // 32769: [0,V)=plain, [V,2V)=negated, 2V=false_emb

typedef unsigned long long ull;

// ---------------- device scratch (static: no runtime allocation allowed) ----------------
__device__ float  g_negT[(VN + 1) * DN];            // rows 0..V-1: vars@Wn+bn ; row V: true_emb
__device__ __half g_P[(size_t)LN * TROWS * 128];    // per-l table @ [W1v_l | W2v_l]  (~50.3MB fp16)
__device__ __half g_ceh[(size_t)VN * CN * DN];      // clause embeddings (fp16, 33.5MB)
__device__ float  g_y[(size_t)VN * 128];            // clause-combiner pre-activation
__device__ float  g_Wc[1024 * 128];                 // [W1c | W2c] concatenated
__device__ int    g_flags[3];
__device__ int    g_mode;                           // 0: 4-byte word, 1: u8, 2: 16-bit

// ---------------- helpers ----------------
__device__ __forceinline__ bool read_mask(const void* p, size_t i, int mode) {
    if (mode == 1) return ((const unsigned char*)p)[i] != 0;
    if (mode == 2) return ((const unsigned short*)p)[i] != 0;
    return ((const unsigned int*)p)[i] != 0;   // int32 or float32: nonzero == true
}
__device__ __forceinline__ float sigf(float x) { return 1.f / (1.f + __expf(-x)); }

__device__ __forceinline__ ull packf2(float lo, float hi) {
    ull r; asm("mov.b64 %0, {%1, %2};" : "=l"(r) : "f"(lo), "f"(hi)); return r;
}
__device__ __forceinline__ void fmaf2(ull& d, ull a, ull b) {
    asm("fma.rn.f32x2 %0, %1, %2, %0;" : "+l"(d) : "l"(a), "l"(b));
}
__device__ __forceinline__ float2 unpackf2(ull v) {
    float lo, hi; asm("mov.b64 {%0, %1}, %2;" : "=f"(lo), "=f"(hi) : "l"(v));
    return make_float2(lo, hi);
}

// ---------------- K0: detect boolean encoding ----------------
__global__ void k_reset() { g_flags[0] = 0; g_flags[1] = 0; g_flags[2] = 0; }

__global__ void k_scan(const unsigned int* __restrict__ w, int nwords) {
    int i = blockIdx.x * blockDim.x + threadIdx.x;
    int bad4 = 0, bad1 = 0, bad2 = 0;
    for (; i < nwords; i += gridDim.x * blockDim.x) {
        unsigned int x = w[i];
        if (!(x == 0u || x == 1u || x == 0x3F800000u)) bad4 = 1;
        if (x & 0xFEFEFEFEu) bad1 = 1;
        unsigned int h0 = x & 0xFFFFu, h1 = x >> 16;
        bool ok0 = (h0 == 0u || h0 == 0x3F80u || h0 == 0x3C00u);
        bool ok1 = (h1 == 0u || h1 == 0x3F80u || h1 == 0x3C00u);
        if (!(ok0 && ok1)) bad2 = 1;
    }
    const unsigned FULL = 0xffffffffu;
    int lane = threadIdx.x & 31;
    bad4 = __any_sync(FULL, bad4);
    bad1 = __any_sync(FULL, bad1);
    bad2 = __any_sync(FULL, bad2);
    if (lane == 0) {
        if (bad4) atomicOr(&g_flags[0], 1);
        if (bad1) atomicOr(&g_flags[1], 1);
        if (bad2) atomicOr(&g_flags[2], 1);
    }
}

__global__ void k_mode() {
    g_mode = (g_flags[0] == 0) ? 0 : ((g_flags[1] == 0) ? 1 : 2);
}

// ---------------- K1a: negT = [variables; false_emb] @ Wn + bn  (16 rows/block) ----------------
__global__ __launch_bounds__(256) void k_neg(const float* __restrict__ vars,
                                             const float* __restrict__ false_emb,
                                             const float* __restrict__ Wn,
                                             const float* __restrict__ bn) {
    __shared__ float Wn_s[64][64];
    __shared__ float src_s[16][64];
    const int tid = threadIdx.x;
    #pragma unroll
    for (int t = 0; t < 4; ++t) {
        int f4 = tid + 256 * t;
        int k = f4 >> 4, q = f4 & 15;
        *(float4*)&Wn_s[k][q * 4] = *(const float4*)(Wn + k * 64 + q * 4);
    }
    {
        int r = tid >> 4, kq = tid & 15;
        int row = blockIdx.x * 16 + r;
        float4 v = make_float4(0.f, 0.f, 0.f, 0.f);
        if (row < VN)       v = *(const float4*)(vars + (size_t)row * 64 + kq * 4);
        else if (row == VN) v = *(const float4*)(false_emb + kq * 4);
        *(float4*)&src_s[r][kq * 4] = v;
    }
    __syncthreads();
    const int rt = tid >> 6, d = tid & 63;
    const float bd = bn[d];
    float acc[4] = {bd, bd, bd, bd};
    #pragma unroll 8
    for (int k = 0; k < 64; ++k) {
        float w = Wn_s[k][d];
        #pragma unroll
        for (int t = 0; t < 4; ++t) acc[t] += src_s[rt * 4 + t][k] * w;
    }
    #pragma unroll
    for (int t = 0; t < 4; ++t) {
        int row = blockIdx.x * 16 + rt * 4 + t;
        if (row <= VN) g_negT[(size_t)row * 64 + d] = acc[t];
    }
}

// ---------------- K1b: P_l = T @ [W1v_l | W2v_l]  -> fp16  (f32x2 FMA) ----------------
__global__ __launch_bounds__(256) void k_build_P(const float* __restrict__ vars,
                                                 const float* __restrict__ false_emb,
                                                 const float* __restrict__ W1v,
                                                 const float* __restrict__ W2v) {
    __shared__ float T_s[64][64];     // 16KB
    __shared__ float W_s[64][128];    // 32KB
    const int tid = threadIdx.x;
    const int l = blockIdx.y;
    const int r0 = blockIdx.x * 64;

    #pragma unroll
    for (int t = 0; t < 8; ++t) {
        int f4 = tid + 256 * t;
        int k = f4 >> 5, cq = f4 & 31;
        const float* src = (cq < 16)
            ? (W1v + ((size_t)(l * 64 + k)) * 64 + cq * 4)
            : (W2v + ((size_t)(l * 64 + k)) * 64 + (cq - 16) * 4);
        *(float4*)&W_s[k][cq * 4] = *(const float4*)src;
    }
    #pragma unroll
    for (int t = 0; t < 4; ++t) {
        int f4 = tid + 256 * t;
        int r = f4 >> 4, kq = f4 & 15;
        int rr = r0 + r;
        float4 v = make_float4(0.f, 0.f, 0.f, 0.f);
        if (rr < VN)           v = *(const float4*)(vars + (size_t)rr * 64 + kq * 4);
        else if (rr < 2 * VN)  v = *(const float4*)(g_negT + (size_t)(rr - VN) * 64 + kq * 4);
        else if (rr == 2 * VN) v = *(const float4*)(false_emb + kq * 4);
        *(float4*)&T_s[r][kq * 4] = v;
    }
    __syncthreads();

    const int rgi = tid >> 4, cgi = tid & 15;
    ull acc2[4][4];
    #pragma unroll
    for (int i = 0; i < 4; ++i)
        #pragma unroll
        for (int j = 0; j < 4; ++j) acc2[i][j] = 0ull;

    #pragma unroll 4
    for (int k = 0; k < 64; ++k) {
        ull aa[4];
        #pragma unroll
        for (int i = 0; i < 4; ++i) {
            float a = T_s[rgi * 4 + i][k];
            aa[i] = packf2(a, a);
        }
        float4 b0 = *(const float4*)&W_s[k][cgi * 8];
        float4 b1 = *(const float4*)&W_s[k][cgi * 8 + 4];
        ull bb[4] = {packf2(b0.x, b0.y), packf2(b0.z, b0.w),
                     packf2(b1.x, b1.y), packf2(b1.z, b1.w)};
        #pragma unroll
        for (int i = 0; i < 4; ++i)
            #pragma unroll
            for (int j = 0; j < 4; ++j) fmaf2(acc2[i][j], aa[i], bb[j]);
    }

    #pragma unroll
    for (int i = 0; i < 4; ++i) {
        int rr = r0 + rgi * 4 + i;
        if (rr < TROWS) {
            float2 f0 = unpackf2(acc2[i][0]);
            float2 f1 = unpackf2(acc2[i][1]);
            float2 f2 = unpackf2(acc2[i][2]);
            float2 f3 = unpackf2(acc2[i][3]);
            __half2 h0 = __floats2half2_rn(f0.x, f0.y);
            __half2 h1 = __floats2half2_rn(f1.x, f1.y);
            __half2 h2 = __floats2half2_rn(f2.x, f2.y);
            __half2 h3 = __floats2half2_rn(f3.x, f3.y);
            uint4 pk;
            pk.x = *(unsigned int*)&h0; pk.y = *(unsigned int*)&h1;
            pk.z = *(unsigned int*)&h2; pk.w = *(unsigned int*)&h3;
            *(uint4*)(g_P + ((size_t)l * TROWS + rr) * 128 + cgi * 8) = pk;
        }
    }
}

// ---------------- Kw: concat W1c|W2c ----------------
__global__ void k_wc(const float* __restrict__ W1c, const float* __restrict__ W2c) {
    int i = blockIdx.x * blockDim.x + threadIdx.x;
    if (i < 1024 * 128) {
        int k = i >> 7, j = i & 127;
        g_Wc[i] = (j < 64) ? W1c[k * 64 + j] : W2c[k * 64 + (j - 64)];
    }
}

// ---------------- K2: clause embeddings (2 clauses per warp), fp16 gathers ----------------
__global__ __launch_bounds__(256) void k_clause(const int* __restrict__ lits,
                                                const void* __restrict__ negm,
                                                const void* __restrict__ vvalid,
                                                const void* __restrict__ cvalid,
                                                const float* __restrict__ b1v,
                                                const float* __restrict__ b2v) {
    const unsigned FULL = 0xffffffffu;
    const int gw = (blockIdx.x * blockDim.x + threadIdx.x) >> 5;  // warp id
    const int lane = threadIdx.x & 31;
    const int c0 = gw * 2, c1 = gw * 2 + 1;
    if (c0 >= VN * CN) return;
    const int mode = g_mode;

    int rowid0 = 2 * VN, rowid1 = 2 * VN;
    if (lane < LN) {
        size_t b0i = (size_t)c0 * LN + lane;
        size_t b1i = (size_t)c1 * LN + lane;
        int i0 = lits[b0i], i1 = lits[b1i];
        bool n0 = read_mask(negm, b0i, mode), n1 = read_mask(negm, b1i, mode);
        bool v0 = read_mask(vvalid, b0i, mode), v1 = read_mask(vvalid, b1i, mode);
        rowid0 = v0 ? (n0 ? i0 + VN : i0) : 2 * VN;
        rowid1 = v1 ? (n1 ? i1 + VN : i1) : 2 * VN;
    }

    const float* bp = (lane < 16) ? (b1v + lane * 4) : (b2v + (lane - 16) * 4);
    float4 bias = *(const float4*)bp;
    float4 accA = bias, accB = bias;
    #pragma unroll
    for (int l = 0; l < LN; ++l) {
        int rA = __shfl_sync(FULL, rowid0, l);
        int rB = __shfl_sync(FULL, rowid1, l);
        uint2 uA = __ldg((const uint2*)(g_P + ((size_t)l * TROWS + rA) * 128) + lane);
        uint2 uB = __ldg((const uint2*)(g_P + ((size_t)l * TROWS + rB) * 128) + lane);
        float2 a0 = __half22float2(*(__half2*)&uA.x);
        float2 a1 = __half22float2(*(__half2*)&uA.y);
        float2 b0 = __half22float2(*(__half2*)&uB.x);
        float2 b1 = __half22float2(*(__half2*)&uB.y);
        accA.x += a0.x; accA.y += a0.y; accA.z += a1.x; accA.w += a1.y;
        accB.x += b0.x; accB.y += b0.y; accB.z += b1.x; accB.w += b1.y;
    }

    float4 linA, linB;
    linA.x = __shfl_down_sync(FULL, accA.x, 16);
    linA.y = __shfl_down_sync(FULL, accA.y, 16);
    linA.z = __shfl_down_sync(FULL, accA.z, 16);
    linA.w = __shfl_down_sync(FULL, accA.w, 16);
    linB.x = __shfl_down_sync(FULL, accB.x, 16);
    linB.y = __shfl_down_sync(FULL, accB.y, 16);
    linB.z = __shfl_down_sync(FULL, accB.z, 16);
    linB.w = __shfl_down_sync(FULL, accB.w, 16);

    float hAx = 0.f, hAy = 0.f, hAz = 0.f, hAw = 0.f, ssA = 0.f;
    float hBx = 0.f, hBy = 0.f, hBz = 0.f, hBw = 0.f, ssB = 0.f;
    if (lane < 16) {
        hAx = sigf(accA.x) + linA.x;
        hAy = sigf(accA.y) + linA.y;
        hAz = sigf(accA.z) + linA.z;
        hAw = sigf(accA.w) + linA.w;
        ssA = hAx * hAx + hAy * hAy + hAz * hAz + hAw * hAw;
        hBx = sigf(accB.x) + linB.x;
        hBy = sigf(accB.y) + linB.y;
        hBz = sigf(accB.z) + linB.z;
        hBw = sigf(accB.w) + linB.w;
        ssB = hBx * hBx + hBy * hBy + hBz * hBz + hBw * hBw;
    }
    #pragma unroll
    for (int o = 16; o; o >>= 1) {
        ssA += __shfl_xor_sync(FULL, ssA, o);
        ssB += __shfl_xor_sync(FULL, ssB, o);
    }
    float invA = rsqrtf(ssA), invB = rsqrtf(ssB);

    bool cvA = read_mask(cvalid, (size_t)c0, mode);
    bool cvB = read_mask(cvalid, (size_t)c1, mode);
    if (lane < 16) {
        float4 oA, oB;
        if (cvA) oA = make_float4(hAx * invA, hAy * invA, hAz * invA, hAw * invA);
        else     oA = *(const float4*)(g_negT + (size_t)VN * 64 + lane * 4);  // true_emb
        if (cvB) oB = make_float4(hBx * invB, hBy * invB, hBz * invB, hBw * invB);
        else     oB = *(const float4*)(g_negT + (size_t)VN * 64 + lane * 4);
        __half2 a0 = __floats2half2_rn(oA.x, oA.y), a1 = __floats2half2_rn(oA.z, oA.w);
        __half2 b0 = __floats2half2_rn(oB.x, oB.y), b1 = __floats2half2_rn(oB.z, oB.w);
        uint2 wa, wb;
        wa.x = *(unsigned int*)&a0; wa.y = *(unsigned int*)&a1;
        wb.x = *(unsigned int*)&b0; wb.y = *(unsigned int*)&b1;
        *((uint2*)(g_ceh + (size_t)c0 * 64) + lane) = wa;
        *((uint2*)(g_ceh + (size_t)c1 * 64) + lane) = wb;
    }
}

// ---------------- K3: [V,1024](fp16) @ [1024,128] -> g_y  (128x128 tiles, f32x2 FMA) ----------------
__global__ __launch_bounds__(256) void k_gemm() {
    __shared__ float A_s[128][32];   // 16KB
    __shared__ float B_s[32][128];   // 16KB
    const int tid = threadIdx.x;
    const int r0 = blockIdx.x * 128;
    const int rgi = tid >> 4, cgi = tid & 15;

    ull acc2[8][4];
    #pragma unroll
    for (int i = 0; i < 8; ++i)
        #pragma unroll
        for (int j = 0; j < 4; ++j) acc2[i][j] = 0ull;

    for (int kc = 0; kc < 1024; kc += 32) {
        // A: 128 rows x 32 halfs = 1024 uint2-groups (4 halfs each)
        #pragma unroll
        for (int t = 0; t < 4; ++t) {
            int g = tid + 256 * t;
            int r = g >> 3, q = g & 7;
            uint2 u = *(const uint2*)(g_ceh + (size_t)(r0 + r) * 1024 + kc + q * 4);
            float2 f0 = __half22float2(*(__half2*)&u.x);
            float2 f1 = __half22float2(*(__half2*)&u.y);
            *(float4*)&A_s[r][q * 4] = make_float4(f0.x, f0.y, f1.x, f1.y);
        }
        #pragma unroll
        for (int t = 0; t < 4; ++t) {
            int f4 = tid + 256 * t;
            int k = f4 >> 5, cq = f4 & 31;
            *(float4*)&B_s[k][cq * 4] =
                *(const float4*)(g_Wc + (size_t)(kc + k) * 128 + cq * 4);
        }
        __syncthreads();
        #pragma unroll 4
        for (int k = 0; k < 32; ++k) {
            ull aa[8];
            #pragma unroll
            for (int i = 0; i < 8; ++i) {
                float a = A_s[rgi * 8 + i][k];
                aa[i] = packf2(a, a);
            }
            float4 b0 = *(const float4*)&B_s[k][cgi * 8];
            float4 b1 = *(const float4*)&B_s[k][cgi * 8 + 4];
            ull bb[4] = {packf2(b0.x, b0.y), packf2(b0.z, b0.w),
                         packf2(b1.x, b1.y), packf2(b1.z, b1.w)};
            #pragma unroll
            for (int i = 0; i < 8; ++i)
                #pragma unroll
                for (int j = 0; j < 4; ++j) fmaf2(acc2[i][j], aa[i], bb[j]);
        }
        __syncthreads();
    }

    #pragma unroll
    for (int i = 0; i < 8; ++i) {
        int r = r0 + rgi * 8 + i;
        float2 f0 = unpackf2(acc2[i][0]);
        float2 f1 = unpackf2(acc2[i][1]);
        float2 f2 = unpackf2(acc2[i][2]);
        float2 f3 = unpackf2(acc2[i][3]);
        float* dst = g_y + (size_t)r * 128 + cgi * 8;
        *(float4*)dst       = make_float4(f0.x, f0.y, f1.x, f1.y);
        *(float4*)(dst + 4) = make_float4(f2.x, f2.y, f3.x, f3.y);
    }
}

// ---------------- K4: final combine + normalize + passthrough ----------------
__global__ __launch_bounds__(256) void k_final(const float* __restrict__ vars,
                                               const void* __restrict__ cvalid,
                                               const float* __restrict__ b1c,
                                               const float* __restrict__ b2c,
                                               float* __restrict__ out) {
    const unsigned FULL = 0xffffffffu;
    const int gw = (blockIdx.x * blockDim.x + threadIdx.x) >> 5;  // variable index
    const int lane = threadIdx.x & 31;
    if (gw >= VN) return;
    const int mode = g_mode;

    const float* bp = (lane < 16) ? (b1c + lane * 4) : (b2c + (lane - 16) * 4);
    float4 acc = *(const float4*)bp;
    float4 yv = *(const float4*)(g_y + (size_t)gw * 128 + lane * 4);
    acc.x += yv.x; acc.y += yv.y; acc.z += yv.z; acc.w += yv.w;

    float4 lin;
    lin.x = __shfl_down_sync(FULL, acc.x, 16);
    lin.y = __shfl_down_sync(FULL, acc.y, 16);
    lin.z = __shfl_down_sync(FULL, acc.z, 16);
    lin.w = __shfl_down_sync(FULL, acc.w, 16);

    float hx = 0.f, hy = 0.f, hz = 0.f, hw = 0.f, ss = 0.f;
    if (lane < 16) {
        hx = sigf(acc.x) + lin.x;
        hy = sigf(acc.y) + lin.y;
        hz = sigf(acc.z) + lin.z;
        hw = sigf(acc.w) + lin.w;
        ss = hx * hx + hy * hy + hz * hz + hw * hw;
    }
    #pragma unroll
    for (int o = 16; o; o >>= 1) ss += __shfl_xor_sync(FULL, ss, o);
    float inv = rsqrtf(ss);

    bool cv = (lane < 16) ? read_mask(cvalid, (size_t)gw * CN + lane, mode) : false;
    bool has = __ballot_sync(FULL, cv) != 0u;

    if (lane < 16) {
        float4 o4;
        if (has) {
            o4 = make_float4(hx * inv, hy * inv, hz * inv, hw * inv);
        } else {
            o4 = *(const float4*)(vars + (size_t)gw * 64 + lane * 4);
        }
        *(float4*)(out + (size_t)gw * 64 + lane * 4) = o4;
    }
}

// ---------------- launch ----------------
extern "C" void kernel_launch(void* const* d_in, const int* in_sizes, int n_in,
                              void* d_out, int out_size) {
    const float* vars      = (const float*)d_in[0];
    const int*   lits      = (const int*)d_in[1];
    const void*  negm      = d_in[2];
    const void*  vval      = d_in[3];
    const void*  cval      = d_in[4];
    const float* Wn        = (const float*)d_in[5];
    const float* bn        = (const float*)d_in[6];
    const float* false_emb = (const float*)d_in[7];
    const float* W1v       = (const float*)d_in[8];
    const float* b1v       = (const float*)d_in[9];
    const float* W2v       = (const float*)d_in[10];
    const float* b2v       = (const float*)d_in[11];
    const float* W1c       = (const float*)d_in[12];
    const float* b1c       = (const float*)d_in[13];
    const float* W2c       = (const float*)d_in[14];
    const float* b2c       = (const float*)d_in[15];
    float* out = (float*)d_out;

    // K0: boolean encoding detection (deterministic, data-driven)
    k_reset<<<1, 1>>>();
    const int nwords = (VN * CN * LN) / 4;
    k_scan<<<1024, 256>>>((const unsigned int*)negm, nwords);
    k_mode<<<1, 1>>>();

    // K1: precompute negation table + per-slot projected tables (fp16) + concat Wc
    k_neg<<<(VN + 1 + 15) / 16, 256>>>(vars, false_emb, Wn, bn);
    k_build_P<<<dim3((TROWS + 63) / 64, LN), 256>>>(vars, false_emb, W1v, W2v);
    k_wc<<<(1024 * 128 + 255) / 256, 256>>>(W1c, W2c);

    // K2: clause embeddings via fp16 gather-and-add (2 clauses/warp)
    k_clause<<<(VN * CN) / 16, 256>>>(lits, negm, vval, cval, b1v, b2v);

    // K3: clause combiner GEMM (128x128 tiles, fp16 A, f32x2 FMA)
    k_gemm<<<VN / 128, 256>>>();

    // K4: final residual combine + normalize + no-clause passthrough
    k_final<<<VN / 8, 256>>>(vars, cval, b1c, b2c, out);
}

// round 7
// speedup vs baseline: 1.2776x; 1.0075x over previous
#include <cuda_runtime.h>
#include <cuda_fp16.h>
#include <cstdint>
#include <cstddef>

#define VN 16384
#define CN 16
#define LN 6
#define DN 64
#define TROWS (2 * VN + 1)   // 32769: [0,V)=plain, [V,2V)=negated, 2V=false_emb

typedef unsigned long long ull;

// ---------------- device scratch (static: no runtime allocation allowed) ----------------
__device__ float  g_negT[(VN + 1) * DN];            // rows 0..V-1: vars@Wn+bn ; row V: true_emb
__device__ __half g_P[(size_t)LN * TROWS * 128];    // per-l table @ [W1v_l | W2v_l]  (~50.3MB fp16)
__device__ __half g_ceh[(size_t)VN * CN * DN];      // clause embeddings (fp16, 33.5MB)
__device__ float  g_y[(size_t)VN * 128];            // clause-combiner pre-activation
__device__ float  g_Wc[1024 * 128];                 // [W1c | W2c] concatenated
__device__ int    g_flags[3];
__device__ int    g_mode;                           // 0: 4-byte word, 1: u8, 2: 16-bit

// ---------------- helpers ----------------
__device__ __forceinline__ bool read_mask(const void* p, size_t i, int mode) {
    if (mode == 1) return ((const unsigned char*)p)[i] != 0;
    if (mode == 2) return ((const unsigned short*)p)[i] != 0;
    return ((const unsigned int*)p)[i] != 0;   // int32 or float32: nonzero == true
}
__device__ __forceinline__ float sigf(float x) { return 1.f / (1.f + __expf(-x)); }

__device__ __forceinline__ ull packf2(float lo, float hi) {
    ull r; asm("mov.b64 %0, {%1, %2};" : "=l"(r) : "f"(lo), "f"(hi)); return r;
}
__device__ __forceinline__ void fmaf2(ull& d, ull a, ull b) {
    asm("fma.rn.f32x2 %0, %1, %2, %0;" : "+l"(d) : "l"(a), "l"(b));
}
__device__ __forceinline__ float2 unpackf2(ull v) {
    float lo, hi; asm("mov.b64 {%0, %1}, %2;" : "=f"(lo), "=f"(hi) : "l"(v));
    return make_float2(lo, hi);
}

// Access policy: evict_last (keep P-table resident in L2). ptxas on sm_103
// only accepts the bare .L2::evict_last qualifier on 256-bit ops, so both the
// ld and st sides use the createpolicy + .L2::cache_hint form instead.
__device__ __forceinline__ ull mk_policy_el() {
    ull p;
    asm("createpolicy.fractional.L2::evict_last.b64 %0, 1.0;" : "=l"(p));
    return p;
}
__device__ __forceinline__ uint2 ldg_P(const __half* p, ull pol) {
    uint2 u;
    asm("ld.global.nc.L2::cache_hint.v2.b32 {%0,%1}, [%2], %3;"
        : "=r"(u.x), "=r"(u.y) : "l"(p), "l"(pol));
    return u;
}
// P-table writes: install as evict_last so it stays in L2
__device__ __forceinline__ void stg_P(__half* p, uint4 v, ull pol) {
    asm volatile("st.global.L2::cache_hint.v4.b32 [%0], {%1,%2,%3,%4}, %5;"
                 :: "l"(p), "r"(v.x), "r"(v.y), "r"(v.z), "r"(v.w), "l"(pol) : "memory");
}
// clause-embedding stream: evict-first, don't pollute L2
__device__ __forceinline__ void stg_cs(__half* p, uint2 v) {
    asm volatile("st.global.cs.v2.b32 [%0], {%1,%2};"
                 :: "l"(p), "r"(v.x), "r"(v.y) : "memory");
}
__device__ __forceinline__ uint2 ldg_cs(const __half* p) {
    uint2 u;
    asm("ld.global.cs.v2.b32 {%0,%1}, [%2];" : "=r"(u.x), "=r"(u.y) : "l"(p));
    return u;
}

// ---------------- K0: detect boolean encoding ----------------
__global__ void k_reset() { g_flags[0] = 0; g_flags[1] = 0; g_flags[2] = 0; }

__global__ void k_scan(const unsigned int* __restrict__ w, int nwords) {
    int i = blockIdx.x * blockDim.x + threadIdx.x;
    int bad4 = 0, bad1 = 0, bad2 = 0;
    for (; i < nwords; i += gridDim.x * blockDim.x) {
        unsigned int x = w[i];
        if (!(x == 0u || x == 1u || x == 0x3F800000u)) bad4 = 1;
        if (x & 0xFEFEFEFEu) bad1 = 1;
        unsigned int h0 = x & 0xFFFFu, h1 = x >> 16;
        bool ok0 = (h0 == 0u || h0 == 0x3F80u || h0 == 0x3C00u);
        bool ok1 = (h1 == 0u || h1 == 0x3F80u || h1 == 0x3C00u);
        if (!(ok0 && ok1)) bad2 = 1;
    }
    const unsigned FULL = 0xffffffffu;
    int lane = threadIdx.x & 31;
    bad4 = __any_sync(FULL, bad4);
    bad1 = __any_sync(FULL, bad1);
    bad2 = __any_sync(FULL, bad2);
    if (lane == 0) {
        if (bad4) atomicOr(&g_flags[0], 1);
        if (bad1) atomicOr(&g_flags[1], 1);
        if (bad2) atomicOr(&g_flags[2], 1);
    }
}

__global__ void k_mode() {
    g_mode = (g_flags[0] == 0) ? 0 : ((g_flags[1] == 0) ? 1 : 2);
}

// ---------------- K1a: negT = [variables; false_emb] @ Wn + bn  (16 rows/block) ----------------
__global__ __launch_bounds__(256) void k_neg(const float* __restrict__ vars,
                                             const float* __restrict__ false_emb,
                                             const float* __restrict__ Wn,
                                             const float* __restrict__ bn) {
    __shared__ float Wn_s[64][64];
    __shared__ float src_s[16][64];
    const int tid = threadIdx.x;
    #pragma unroll
    for (int t = 0; t < 4; ++t) {
        int f4 = tid + 256 * t;
        int k = f4 >> 4, q = f4 & 15;
        *(float4*)&Wn_s[k][q * 4] = *(const float4*)(Wn + k * 64 + q * 4);
    }
    {
        int r = tid >> 4, kq = tid & 15;
        int row = blockIdx.x * 16 + r;
        float4 v = make_float4(0.f, 0.f, 0.f, 0.f);
        if (row < VN)       v = *(const float4*)(vars + (size_t)row * 64 + kq * 4);
        else if (row == VN) v = *(const float4*)(false_emb + kq * 4);
        *(float4*)&src_s[r][kq * 4] = v;
    }
    __syncthreads();
    const int rt = tid >> 6, d = tid & 63;
    const float bd = bn[d];
    float acc[4] = {bd, bd, bd, bd};
    #pragma unroll 8
    for (int k = 0; k < 64; ++k) {
        float w = Wn_s[k][d];
        #pragma unroll
        for (int t = 0; t < 4; ++t) acc[t] += src_s[rt * 4 + t][k] * w;
    }
    #pragma unroll
    for (int t = 0; t < 4; ++t) {
        int row = blockIdx.x * 16 + rt * 4 + t;
        if (row <= VN) g_negT[(size_t)row * 64 + d] = acc[t];
    }
}

// ---------------- K1b: P_l = T @ [W1v_l | W2v_l]  -> fp16  (f32x2 FMA, evict_last store) ----------------
__global__ __launch_bounds__(256) void k_build_P(const float* __restrict__ vars,
                                                 const float* __restrict__ false_emb,
                                                 const float* __restrict__ W1v,
                                                 const float* __restrict__ W2v) {
    __shared__ float T_s[64][64];     // 16KB
    __shared__ float W_s[64][128];    // 32KB
    const int tid = threadIdx.x;
    const int l = blockIdx.y;
    const int r0 = blockIdx.x * 64;

    #pragma unroll
    for (int t = 0; t < 8; ++t) {
        int f4 = tid + 256 * t;
        int k = f4 >> 5, cq = f4 & 31;
        const float* src = (cq < 16)
            ? (W1v + ((size_t)(l * 64 + k)) * 64 + cq * 4)
            : (W2v + ((size_t)(l * 64 + k)) * 64 + (cq - 16) * 4);
        *(float4*)&W_s[k][cq * 4] = *(const float4*)src;
    }
    #pragma unroll
    for (int t = 0; t < 4; ++t) {
        int f4 = tid + 256 * t;
        int r = f4 >> 4, kq = f4 & 15;
        int rr = r0 + r;
        float4 v = make_float4(0.f, 0.f, 0.f, 0.f);
        if (rr < VN)           v = *(const float4*)(vars + (size_t)rr * 64 + kq * 4);
        else if (rr < 2 * VN)  v = *(const float4*)(g_negT + (size_t)(rr - VN) * 64 + kq * 4);
        else if (rr == 2 * VN) v = *(const float4*)(false_emb + kq * 4);
        *(float4*)&T_s[r][kq * 4] = v;
    }
    __syncthreads();

    const int rgi = tid >> 4, cgi = tid & 15;
    const ull pol = mk_policy_el();
    ull acc2[4][4];
    #pragma unroll
    for (int i = 0; i < 4; ++i)
        #pragma unroll
        for (int j = 0; j < 4; ++j) acc2[i][j] = 0ull;

    #pragma unroll 4
    for (int k = 0; k < 64; ++k) {
        ull aa[4];
        #pragma unroll
        for (int i = 0; i < 4; ++i) {
            float a = T_s[rgi * 4 + i][k];
            aa[i] = packf2(a, a);
        }
        float4 b0 = *(const float4*)&W_s[k][cgi * 8];
        float4 b1 = *(const float4*)&W_s[k][cgi * 8 + 4];
        ull bb[4] = {packf2(b0.x, b0.y), packf2(b0.z, b0.w),
                     packf2(b1.x, b1.y), packf2(b1.z, b1.w)};
        #pragma unroll
        for (int i = 0; i < 4; ++i)
            #pragma unroll
            for (int j = 0; j < 4; ++j) fmaf2(acc2[i][j], aa[i], bb[j]);
    }

    #pragma unroll
    for (int i = 0; i < 4; ++i) {
        int rr = r0 + rgi * 4 + i;
        if (rr < TROWS) {
            float2 f0 = unpackf2(acc2[i][0]);
            float2 f1 = unpackf2(acc2[i][1]);
            float2 f2 = unpackf2(acc2[i][2]);
            float2 f3 = unpackf2(acc2[i][3]);
            __half2 h0 = __floats2half2_rn(f0.x, f0.y);
            __half2 h1 = __floats2half2_rn(f1.x, f1.y);
            __half2 h2 = __floats2half2_rn(f2.x, f2.y);
            __half2 h3 = __floats2half2_rn(f3.x, f3.y);
            uint4 pk;
            pk.x = *(unsigned int*)&h0; pk.y = *(unsigned int*)&h1;
            pk.z = *(unsigned int*)&h2; pk.w = *(unsigned int*)&h3;
            stg_P(g_P + ((size_t)l * TROWS + rr) * 128 + cgi * 8, pk, pol);
        }
    }
}

// ---------------- Kw: concat W1c|W2c ----------------
__global__ void k_wc(const float* __restrict__ W1c, const float* __restrict__ W2c) {
    int i = blockIdx.x * blockDim.x + threadIdx.x;
    if (i < 1024 * 128) {
        int k = i >> 7, j = i & 127;
        g_Wc[i] = (j < 64) ? W1c[k * 64 + j] : W2c[k * 64 + (j - 64)];
    }
}

// ---------------- K2: clause embeddings (4 clauses per warp), fp16 gathers ----------------
__global__ __launch_bounds__(256) void k_clause(const int* __restrict__ lits,
                                                const void* __restrict__ negm,
                                                const void* __restrict__ vvalid,
                                                const void* __restrict__ cvalid,
                                                const float* __restrict__ b1v,
                                                const float* __restrict__ b2v) {
    const unsigned FULL = 0xffffffffu;
    const int gw = (blockIdx.x * blockDim.x + threadIdx.x) >> 5;  // warp id
    const int lane = threadIdx.x & 31;
    const int cb = gw * 4;
    if (cb >= VN * CN) return;
    const int mode = g_mode;
    const ull pol = mk_policy_el();

    int rowid[4];
    #pragma unroll
    for (int j = 0; j < 4; ++j) {
        rowid[j] = 2 * VN;
        if (lane < LN) {
            size_t bi = (size_t)(cb + j) * LN + lane;
            int idx = lits[bi];
            bool neg = read_mask(negm, bi, mode);
            bool val = read_mask(vvalid, bi, mode);
            rowid[j] = val ? (neg ? idx + VN : idx) : 2 * VN;
        }
    }

    const float* bp = (lane < 16) ? (b1v + lane * 4) : (b2v + (lane - 16) * 4);
    float4 bias = *(const float4*)bp;
    float4 acc[4] = {bias, bias, bias, bias};
    #pragma unroll
    for (int l = 0; l < LN; ++l) {
        #pragma unroll
        for (int j = 0; j < 4; ++j) {
            int r = __shfl_sync(FULL, rowid[j], l);
            uint2 u = ldg_P(g_P + ((size_t)l * TROWS + r) * 128 + lane * 4, pol);
            float2 f0 = __half22float2(*(__half2*)&u.x);
            float2 f1 = __half22float2(*(__half2*)&u.y);
            acc[j].x += f0.x; acc[j].y += f0.y; acc[j].z += f1.x; acc[j].w += f1.y;
        }
    }

    float h[4][4], ss[4];
    #pragma unroll
    for (int j = 0; j < 4; ++j) {
        float4 lin;
        lin.x = __shfl_down_sync(FULL, acc[j].x, 16);
        lin.y = __shfl_down_sync(FULL, acc[j].y, 16);
        lin.z = __shfl_down_sync(FULL, acc[j].z, 16);
        lin.w = __shfl_down_sync(FULL, acc[j].w, 16);
        float s = 0.f;
        h[j][0] = h[j][1] = h[j][2] = h[j][3] = 0.f;
        if (lane < 16) {
            h[j][0] = sigf(acc[j].x) + lin.x;
            h[j][1] = sigf(acc[j].y) + lin.y;
            h[j][2] = sigf(acc[j].z) + lin.z;
            h[j][3] = sigf(acc[j].w) + lin.w;
            s = h[j][0]*h[j][0] + h[j][1]*h[j][1] + h[j][2]*h[j][2] + h[j][3]*h[j][3];
        }
        ss[j] = s;
    }
    #pragma unroll
    for (int o = 16; o; o >>= 1) {
        #pragma unroll
        for (int j = 0; j < 4; ++j) ss[j] += __shfl_xor_sync(FULL, ss[j], o);
    }

    #pragma unroll
    for (int j = 0; j < 4; ++j) {
        float inv = rsqrtf(ss[j]);
        bool cv = read_mask(cvalid, (size_t)(cb + j), mode);
        if (lane < 16) {
            float4 o4;
            if (cv) o4 = make_float4(h[j][0]*inv, h[j][1]*inv, h[j][2]*inv, h[j][3]*inv);
            else    o4 = *(const float4*)(g_negT + (size_t)VN * 64 + lane * 4);  // true_emb
            __half2 p0 = __floats2half2_rn(o4.x, o4.y);
            __half2 p1 = __floats2half2_rn(o4.z, o4.w);
            uint2 w;
            w.x = *(unsigned int*)&p0; w.y = *(unsigned int*)&p1;
            stg_cs(g_ceh + (size_t)(cb + j) * 64 + lane * 4, w);
        }
    }
}

// ---------------- K3: [V,1024](fp16) @ [1024,128] -> g_y  (128x128 tiles, f32x2 FMA) ----------------
__global__ __launch_bounds__(256) void k_gemm() {
    __shared__ float A_s[128][32];   // 16KB
    __shared__ float B_s[32][128];   // 16KB
    const int tid = threadIdx.x;
    const int r0 = blockIdx.x * 128;
    const int rgi = tid >> 4, cgi = tid & 15;

    ull acc2[8][4];
    #pragma unroll
    for (int i = 0; i < 8; ++i)
        #pragma unroll
        for (int j = 0; j < 4; ++j) acc2[i][j] = 0ull;

    for (int kc = 0; kc < 1024; kc += 32) {
        // A: 128 rows x 32 halfs, streaming read (single use)
        #pragma unroll
        for (int t = 0; t < 4; ++t) {
            int g = tid + 256 * t;
            int r = g >> 3, q = g & 7;
            uint2 u = ldg_cs(g_ceh + (size_t)(r0 + r) * 1024 + kc + q * 4);
            float2 f0 = __half22float2(*(__half2*)&u.x);
            float2 f1 = __half22float2(*(__half2*)&u.y);
            *(float4*)&A_s[r][q * 4] = make_float4(f0.x, f0.y, f1.x, f1.y);
        }
        #pragma unroll
        for (int t = 0; t < 4; ++t) {
            int f4 = tid + 256 * t;
            int k = f4 >> 5, cq = f4 & 31;
            *(float4*)&B_s[k][cq * 4] =
                *(const float4*)(g_Wc + (size_t)(kc + k) * 128 + cq * 4);
        }
        __syncthreads();
        #pragma unroll 4
        for (int k = 0; k < 32; ++k) {
            ull aa[8];
            #pragma unroll
            for (int i = 0; i < 8; ++i) {
                float a = A_s[rgi * 8 + i][k];
                aa[i] = packf2(a, a);
            }
            float4 b0 = *(const float4*)&B_s[k][cgi * 8];
            float4 b1 = *(const float4*)&B_s[k][cgi * 8 + 4];
            ull bb[4] = {packf2(b0.x, b0.y), packf2(b0.z, b0.w),
                         packf2(b1.x, b1.y), packf2(b1.z, b1.w)};
            #pragma unroll
            for (int i = 0; i < 8; ++i)
                #pragma unroll
                for (int j = 0; j < 4; ++j) fmaf2(acc2[i][j], aa[i], bb[j]);
        }
        __syncthreads();
    }

    #pragma unroll
    for (int i = 0; i < 8; ++i) {
        int r = r0 + rgi * 8 + i;
        float2 f0 = unpackf2(acc2[i][0]);
        float2 f1 = unpackf2(acc2[i][1]);
        float2 f2 = unpackf2(acc2[i][2]);
        float2 f3 = unpackf2(acc2[i][3]);
        float* dst = g_y + (size_t)r * 128 + cgi * 8;
        *(float4*)dst       = make_float4(f0.x, f0.y, f1.x, f1.y);
        *(float4*)(dst + 4) = make_float4(f2.x, f2.y, f3.x, f3.y);
    }
}

// ---------------- K4: final combine + normalize + passthrough ----------------
__global__ __launch_bounds__(256) void k_final(const float* __restrict__ vars,
                                               const void* __restrict__ cvalid,
                                               const float* __restrict__ b1c,
                                               const float* __restrict__ b2c,
                                               float* __restrict__ out) {
    const unsigned FULL = 0xffffffffu;
    const int gw = (blockIdx.x * blockDim.x + threadIdx.x) >> 5;  // variable index
    const int lane = threadIdx.x & 31;
    if (gw >= VN) return;
    const int mode = g_mode;

    const float* bp = (lane < 16) ? (b1c + lane * 4) : (b2c + (lane - 16) * 4);
    float4 acc = *(const float4*)bp;
    float4 yv = *(const float4*)(g_y + (size_t)gw * 128 + lane * 4);
    acc.x += yv.x; acc.y += yv.y; acc.z += yv.z; acc.w += yv.w;

    float4 lin;
    lin.x = __shfl_down_sync(FULL, acc.x, 16);
    lin.y = __shfl_down_sync(FULL, acc.y, 16);
    lin.z = __shfl_down_sync(FULL, acc.z, 16);
    lin.w = __shfl_down_sync(FULL, acc.w, 16);

    float hx = 0.f, hy = 0.f, hz = 0.f, hw = 0.f, ss = 0.f;
    if (lane < 16) {
        hx = sigf(acc.x) + lin.x;
        hy = sigf(acc.y) + lin.y;
        hz = sigf(acc.z) + lin.z;
        hw = sigf(acc.w) + lin.w;
        ss = hx * hx + hy * hy + hz * hz + hw * hw;
    }
    #pragma unroll
    for (int o = 16; o; o >>= 1) ss += __shfl_xor_sync(FULL, ss, o);
    float inv = rsqrtf(ss);

    bool cv = (lane < 16) ? read_mask(cvalid, (size_t)gw * CN + lane, mode) : false;
    bool has = __ballot_sync(FULL, cv) != 0u;

    if (lane < 16) {
        float4 o4;
        if (has) {
            o4 = make_float4(hx * inv, hy * inv, hz * inv, hw * inv);
        } else {
            o4 = *(const float4*)(vars + (size_t)gw * 64 + lane * 4);
        }
        *(float4*)(out + (size_t)gw * 64 + lane * 4) = o4;
    }
}

// ---------------- launch ----------------
extern "C" void kernel_launch(void* const* d_in, const int* in_sizes, int n_in,
                              void* d_out, int out_size) {
    const float* vars      = (const float*)d_in[0];
    const int*   lits      = (const int*)d_in[1];
    const void*  negm      = d_in[2];
    const void*  vval      = d_in[3];
    const void*  cval      = d_in[4];
    const float* Wn        = (const float*)d_in[5];
    const float* bn        = (const float*)d_in[6];
    const float* false_emb = (const float*)d_in[7];
    const float* W1v       = (const float*)d_in[8];
    const float* b1v       = (const float*)d_in[9];
    const float* W2v       = (const float*)d_in[10];
    const float* b2v       = (const float*)d_in[11];
    const float* W1c       = (const float*)d_in[12];
    const float* b1c       = (const float*)d_in[13];
    const float* W2c       = (const float*)d_in[14];
    const float* b2c       = (const float*)d_in[15];
    float* out = (float*)d_out;

    // K0: boolean encoding detection (deterministic, data-driven)
    k_reset<<<1, 1>>>();
    const int nwords = (VN * CN * LN) / 4;
    k_scan<<<1024, 256>>>((const unsigned int*)negm, nwords);
    k_mode<<<1, 1>>>();

    // K1: precompute negation table + per-slot projected tables (fp16, L2-resident) + concat Wc
    k_neg<<<(VN + 1 + 15) / 16, 256>>>(vars, false_emb, Wn, bn);
    k_build_P<<<dim3((TROWS + 63) / 64, LN), 256>>>(vars, false_emb, W1v, W2v);
    k_wc<<<(1024 * 128 + 255) / 256, 256>>>(W1c, W2c);

    // K2: clause embeddings via fp16 gather-and-add (4 clauses/warp)
    k_clause<<<(VN * CN) / 32, 256>>>(lits, negm, vval, cval, b1v, b2v);

    // K3: clause combiner GEMM (128x128 tiles, fp16 A streaming, f32x2 FMA)
    k_gemm<<<VN / 128, 256>>>();

    // K4: final residual combine + normalize + no-clause passthrough
    k_final<<<VN / 8, 256>>>(vars, cval, b1c, b2c, out);
}

// round 9
// speedup vs baseline: 2.4725x; 1.9352x over previous
#include <cuda_runtime.h>
#include <cuda_fp16.h>
#include <cstdint>
#include <cstddef>

#define VN 16384
#define CN 16
#define LN 6
#define DN 64
#define TROWS (2 * VN + 1)   // 32769: [0,V)=plain, [V,2V)=negated, 2V=false_emb
#define AROWS 16512          // 129*128 padded A rows (row VN = false_emb)
#define PADK 72              // padded smem row stride (halfs): conflict-free ldmatrix

typedef unsigned long long ull;

// ---------------- device scratch ----------------
__device__ __half g_P[(size_t)LN * TROWS * 128];    // gather tables (50.3MB fp16)
__device__ __half g_ceh[(size_t)VN * CN * DN];      // clause embeddings fp16 (33.5MB)
__device__ float  g_y[(size_t)VN * 128];            // clause-combiner pre-activation
__device__ __half g_Wch[128 * 1024];                // [W1c|W2c]^T: [n][k] fp16
__device__ __half g_Ut[1536 * 64];                  // B operand [n][k]: j<6 W_l ; j>=6 Wn@W_l
__device__ __half g_varsh[(size_t)AROWS * 64];      // fp16 vars (+false row, zero pad)
__device__ float  g_c[768];                         // bias bn@W_l per col (negated half)
__device__ float  g_true[64];                       // true_emb = false_emb @ Wn + bn
__device__ int    g_flags[3];
__device__ int    g_mode;

// ---------------- helpers ----------------
__device__ __forceinline__ bool read_mask(const void* p, size_t i, int mode) {
    if (mode == 1) return ((const unsigned char*)p)[i] != 0;
    if (mode == 2) return ((const unsigned short*)p)[i] != 0;
    return ((const unsigned int*)p)[i] != 0;
}
__device__ __forceinline__ float sigf(float x) { return 1.f / (1.f + __expf(-x)); }

__device__ __forceinline__ ull mk_policy_el() {
    ull p;
    asm("createpolicy.fractional.L2::evict_last.b64 %0, 1.0;" : "=l"(p));
    return p;
}
__device__ __forceinline__ uint2 ldg_P(const __half* p, ull pol) {
    uint2 u;
    asm("ld.global.nc.L2::cache_hint.v2.b32 {%0,%1}, [%2], %3;"
        : "=r"(u.x), "=r"(u.y) : "l"(p), "l"(pol));
    return u;
}
__device__ __forceinline__ void stg_cs(__half* p, uint2 v) {
    asm volatile("st.global.cs.v2.b32 [%0], {%1,%2};"
                 :: "l"(p), "r"(v.x), "r"(v.y) : "memory");
}
__device__ __forceinline__ uint32_t smem_u32(const void* p) {
    uint32_t a;
    asm("{ .reg .u64 t; cvta.to.shared.u64 t, %1; cvt.u32.u64 %0, t; }"
        : "=r"(a) : "l"(p));
    return a;
}

// ---------------- shared HMMA warptile: 32x64 per warp over one K=64 stage ----------------
// As: [128][PADK] halfs (row-major, k contiguous); Bs: [128][PADK] (n-major, k contiguous)
__device__ __forceinline__ void warptile_mma(uint32_t as_u32, uint32_t bs_u32,
                                             int mg, int ng, int lane,
                                             float acc[2][8][4]) {
    #pragma unroll
    for (int kc = 0; kc < 64; kc += 16) {
        uint32_t afrag[2][4];
        #pragma unroll
        for (int mt = 0; mt < 2; ++mt) {
            int row = mg * 32 + mt * 16 + (lane & 15);
            int col = kc + (lane >> 4) * 8;
            uint32_t addr = as_u32 + (uint32_t)(row * PADK + col) * 2u;
            asm volatile("ldmatrix.sync.aligned.m8n8.x4.shared.b16 {%0,%1,%2,%3}, [%4];"
                : "=r"(afrag[mt][0]), "=r"(afrag[mt][1]),
                  "=r"(afrag[mt][2]), "=r"(afrag[mt][3])
                : "r"(addr));
        }
        #pragma unroll
        for (int nt = 0; nt < 8; ++nt) {
            int rowb = ng * 64 + nt * 8 + (lane & 7);
            int colb = kc + ((lane >> 3) & 1) * 8;
            uint32_t baddr = bs_u32 + (uint32_t)(rowb * PADK + colb) * 2u;
            uint32_t b0, b1;
            asm volatile("ldmatrix.sync.aligned.m8n8.x2.shared.b16 {%0,%1}, [%2];"
                : "=r"(b0), "=r"(b1) : "r"(baddr));
            #pragma unroll
            for (int mt = 0; mt < 2; ++mt) {
                asm volatile(
                    "mma.sync.aligned.m16n8k16.row.col.f32.f16.f16.f32 "
                    "{%0,%1,%2,%3}, {%4,%5,%6,%7}, {%8,%9}, {%0,%1,%2,%3};"
                    : "+f"(acc[mt][nt][0]), "+f"(acc[mt][nt][1]),
                      "+f"(acc[mt][nt][2]), "+f"(acc[mt][nt][3])
                    : "r"(afrag[mt][0]), "r"(afrag[mt][1]),
                      "r"(afrag[mt][2]), "r"(afrag[mt][3]),
                      "r"(b0), "r"(b1));
            }
        }
    }
}

// ---------------- K0: detect boolean encoding ----------------
__global__ void k_reset() { g_flags[0] = 0; g_flags[1] = 0; g_flags[2] = 0; }

__global__ void k_scan(const unsigned int* __restrict__ w, int nwords) {
    int i = blockIdx.x * blockDim.x + threadIdx.x;
    int bad4 = 0, bad1 = 0, bad2 = 0;
    for (; i < nwords; i += gridDim.x * blockDim.x) {
        unsigned int x = w[i];
        if (!(x == 0u || x == 1u || x == 0x3F800000u)) bad4 = 1;
        if (x & 0xFEFEFEFEu) bad1 = 1;
        unsigned int h0 = x & 0xFFFFu, h1 = x >> 16;
        bool ok0 = (h0 == 0u || h0 == 0x3F80u || h0 == 0x3C00u);
        bool ok1 = (h1 == 0u || h1 == 0x3F80u || h1 == 0x3C00u);
        if (!(ok0 && ok1)) bad2 = 1;
    }
    const unsigned FULL = 0xffffffffu;
    int lane = threadIdx.x & 31;
    bad4 = __any_sync(FULL, bad4);
    bad1 = __any_sync(FULL, bad1);
    bad2 = __any_sync(FULL, bad2);
    if (lane == 0) {
        if (bad4) atomicOr(&g_flags[0], 1);
        if (bad1) atomicOr(&g_flags[1], 1);
        if (bad2) atomicOr(&g_flags[2], 1);
    }
}

__global__ void k_mode() {
    g_mode = (g_flags[0] == 0) ? 0 : ((g_flags[1] == 0) ? 1 : 2);
}

// ---------------- K1a: prep Ut / c / true_emb ----------------
__global__ __launch_bounds__(64) void k_prep(const float* __restrict__ W1v,
                                             const float* __restrict__ W2v,
                                             const float* __restrict__ Wn,
                                             const float* __restrict__ bn,
                                             const float* __restrict__ false_emb) {
    const int n = blockIdx.x;          // 0..1535
    const int j = n >> 7, col = n & 127;
    const int k = threadIdx.x;         // 0..63
    const int l = (j >= 6) ? j - 6 : j;

    float v;
    if (j < 6) {
        v = (col < 64) ? W1v[(l * 64 + k) * 64 + col]
                       : W2v[(l * 64 + k) * 64 + col - 64];
    } else {
        float s = 0.f;
        #pragma unroll 8
        for (int m = 0; m < 64; ++m) {
            float wl = (col < 64) ? W1v[(l * 64 + m) * 64 + col]
                                  : W2v[(l * 64 + m) * 64 + col - 64];
            s += Wn[k * 64 + m] * wl;
        }
        v = s;
    }
    g_Ut[n * 64 + k] = __float2half(v);

    if (j >= 6 && k == 0) {
        float s = 0.f;
        for (int m = 0; m < 64; ++m) {
            float wl = (col < 64) ? W1v[(l * 64 + m) * 64 + col]
                                  : W2v[(l * 64 + m) * 64 + col - 64];
            s += bn[m] * wl;
        }
        g_c[(j - 6) * 128 + col] = s;
    }
    if (n == 0) {
        float s = 0.f;
        for (int m = 0; m < 64; ++m) s += false_emb[m] * Wn[m * 64 + k];
        g_true[k] = s + bn[k];
    }
}

// ---------------- K1b: vars -> fp16 padded table ----------------
__global__ __launch_bounds__(256) void k_varsh(const float* __restrict__ vars,
                                               const float* __restrict__ false_emb) {
    int idx = blockIdx.x * blockDim.x + threadIdx.x;   // one per 8 halfs
    if (idx >= AROWS * 8) return;
    int row = idx >> 3, q = idx & 7;
    __half2 h0, h1, h2, h3;
    if (row < VN || row == VN) {
        const float* src = (row < VN) ? vars + (size_t)row * 64 + q * 8
                                      : false_emb + q * 8;
        float4 f0 = *(const float4*)src;
        float4 f1 = *(const float4*)(src + 4);
        h0 = __floats2half2_rn(f0.x, f0.y); h1 = __floats2half2_rn(f0.z, f0.w);
        h2 = __floats2half2_rn(f1.x, f1.y); h3 = __floats2half2_rn(f1.z, f1.w);
    } else {
        h0 = h1 = h2 = h3 = __floats2half2_rn(0.f, 0.f);
    }
    uint4 pk;
    pk.x = *(unsigned int*)&h0; pk.y = *(unsigned int*)&h1;
    pk.z = *(unsigned int*)&h2; pk.w = *(unsigned int*)&h3;
    *(uint4*)(g_varsh + (size_t)row * 64 + q * 8) = pk;
}

// ---------------- Kw: Wch[n][k] fp16 ----------------
__global__ void k_wch(const float* __restrict__ W1c, const float* __restrict__ W2c) {
    int i = blockIdx.x * blockDim.x + threadIdx.x;
    if (i < 128 * 1024) {
        int n = i >> 10, k = i & 1023;
        float v = (n < 64) ? W1c[k * 64 + n] : W2c[k * 64 + (n - 64)];
        g_Wch[i] = __float2half(v);
    }
}

// ---------------- K1c: P table via HMMA. grid (129, 12), 256 thr ----------------
__global__ __launch_bounds__(256) void k_mma_P() {
    __shared__ __align__(16) __half As[128 * PADK];
    __shared__ __align__(16) __half Bs[128 * PADK];
    const int tid = threadIdx.x;
    const int wid = tid >> 5, lane = tid & 31;
    const int mg = wid & 3, ng = wid >> 2;
    const int j = blockIdx.y;
    const int l = (j >= 6) ? j - 6 : j;
    const bool negh = (j >= 6);
    const int r0 = blockIdx.x * 128;

    // stage A (varsh rows r0..r0+127) and B (Ut rows j*128..+127)
    {
        int row = tid >> 1, off = (tid & 1) * 32;
        const __half* srcA = g_varsh + (size_t)(r0 + row) * 64 + off;
        const __half* srcB = g_Ut + (size_t)(j * 128 + row) * 64 + off;
        #pragma unroll
        for (int i = 0; i < 4; ++i) {
            *(uint4*)&As[row * PADK + off + i * 8] = *(const uint4*)(srcA + i * 8);
            *(uint4*)&Bs[row * PADK + off + i * 8] = *(const uint4*)(srcB + i * 8);
        }
    }
    __syncthreads();

    float acc[2][8][4];
    #pragma unroll
    for (int a = 0; a < 2; ++a)
        #pragma unroll
        for (int b = 0; b < 8; ++b)
            #pragma unroll
            for (int d = 0; d < 4; ++d) acc[a][b][d] = 0.f;

    warptile_mma(smem_u32(As), smem_u32(Bs), mg, ng, lane, acc);

    // epilogue: rows r (=T/4) and r+8 per m-tile; cols ng*64 + nt*8 + (T%4)*2
    #pragma unroll
    for (int mt = 0; mt < 2; ++mt) {
        int rr = r0 + mg * 32 + mt * 16 + (lane >> 2);
        #pragma unroll
        for (int half_sel = 0; half_sel < 2; ++half_sel) {
            int rrr = rr + half_sel * 8;
            long target = -1;
            if (!negh) {
                if (rrr < VN) target = rrr;
                else if (rrr == VN) target = 2 * VN;
            } else if (rrr < VN) {
                target = (long)VN + rrr;
            }
            if (target < 0) continue;
            __half* dstrow = g_P + ((size_t)l * TROWS + target) * 128;
            #pragma unroll
            for (int nt = 0; nt < 8; ++nt) {
                int cc = ng * 64 + nt * 8 + (lane & 3) * 2;
                float v0 = acc[mt][nt][half_sel * 2 + 0];
                float v1 = acc[mt][nt][half_sel * 2 + 1];
                if (negh) { v0 += g_c[l * 128 + cc]; v1 += g_c[l * 128 + cc + 1]; }
                __half2 h = __floats2half2_rn(v0, v1);
                *(__half2*)(dstrow + cc) = h;
            }
        }
    }
}

// ---------------- K2: clause embeddings (4 clauses per warp), fp16 gathers ----------------
__global__ __launch_bounds__(256) void k_clause(const int* __restrict__ lits,
                                                const void* __restrict__ negm,
                                                const void* __restrict__ vvalid,
                                                const void* __restrict__ cvalid,
                                                const float* __restrict__ b1v,
                                                const float* __restrict__ b2v) {
    const unsigned FULL = 0xffffffffu;
    const int gw = (blockIdx.x * blockDim.x + threadIdx.x) >> 5;
    const int lane = threadIdx.x & 31;
    const int cb = gw * 4;
    if (cb >= VN * CN) return;
    const int mode = g_mode;
    const ull pol = mk_policy_el();

    int rowid[4];
    #pragma unroll
    for (int j = 0; j < 4; ++j) {
        rowid[j] = 2 * VN;
        if (lane < LN) {
            size_t bi = (size_t)(cb + j) * LN + lane;
            int idx = lits[bi];
            bool neg = read_mask(negm, bi, mode);
            bool val = read_mask(vvalid, bi, mode);
            rowid[j] = val ? (neg ? idx + VN : idx) : 2 * VN;
        }
    }

    const float* bp = (lane < 16) ? (b1v + lane * 4) : (b2v + (lane - 16) * 4);
    float4 bias = *(const float4*)bp;
    float4 acc[4] = {bias, bias, bias, bias};
    #pragma unroll
    for (int l = 0; l < LN; ++l) {
        #pragma unroll
        for (int j = 0; j < 4; ++j) {
            int r = __shfl_sync(FULL, rowid[j], l);
            uint2 u = ldg_P(g_P + ((size_t)l * TROWS + r) * 128 + lane * 4, pol);
            float2 f0 = __half22float2(*(__half2*)&u.x);
            float2 f1 = __half22float2(*(__half2*)&u.y);
            acc[j].x += f0.x; acc[j].y += f0.y; acc[j].z += f1.x; acc[j].w += f1.y;
        }
    }

    float h[4][4], ss[4];
    #pragma unroll
    for (int j = 0; j < 4; ++j) {
        float4 lin;
        lin.x = __shfl_down_sync(FULL, acc[j].x, 16);
        lin.y = __shfl_down_sync(FULL, acc[j].y, 16);
        lin.z = __shfl_down_sync(FULL, acc[j].z, 16);
        lin.w = __shfl_down_sync(FULL, acc[j].w, 16);
        float s = 0.f;
        h[j][0] = h[j][1] = h[j][2] = h[j][3] = 0.f;
        if (lane < 16) {
            h[j][0] = sigf(acc[j].x) + lin.x;
            h[j][1] = sigf(acc[j].y) + lin.y;
            h[j][2] = sigf(acc[j].z) + lin.z;
            h[j][3] = sigf(acc[j].w) + lin.w;
            s = h[j][0]*h[j][0] + h[j][1]*h[j][1] + h[j][2]*h[j][2] + h[j][3]*h[j][3];
        }
        ss[j] = s;
    }
    #pragma unroll
    for (int o = 16; o; o >>= 1) {
        #pragma unroll
        for (int j = 0; j < 4; ++j) ss[j] += __shfl_xor_sync(FULL, ss[j], o);
    }

    #pragma unroll
    for (int j = 0; j < 4; ++j) {
        float inv = rsqrtf(ss[j]);
        bool cv = read_mask(cvalid, (size_t)(cb + j), mode);
        if (lane < 16) {
            float4 o4;
            if (cv) o4 = make_float4(h[j][0]*inv, h[j][1]*inv, h[j][2]*inv, h[j][3]*inv);
            else    o4 = *(const float4*)(g_true + lane * 4);
            __half2 p0 = __floats2half2_rn(o4.x, o4.y);
            __half2 p1 = __floats2half2_rn(o4.z, o4.w);
            uint2 w;
            w.x = *(unsigned int*)&p0; w.y = *(unsigned int*)&p1;
            stg_cs(g_ceh + (size_t)(cb + j) * 64 + lane * 4, w);
        }
    }
}

// ---------------- K3: [V,1024](fp16) @ Wch^T -> g_y via HMMA. grid 128, 256 thr ----------------
__global__ __launch_bounds__(256) void k_gemm() {
    __shared__ __align__(16) __half As[128 * PADK];
    __shared__ __align__(16) __half Bs[128 * PADK];
    const int tid = threadIdx.x;
    const int wid = tid >> 5, lane = tid & 31;
    const int mg = wid & 3, ng = wid >> 2;
    const int r0 = blockIdx.x * 128;

    float acc[2][8][4];
    #pragma unroll
    for (int a = 0; a < 2; ++a)
        #pragma unroll
        for (int b = 0; b < 8; ++b)
            #pragma unroll
            for (int d = 0; d < 4; ++d) acc[a][b][d] = 0.f;

    const int row = tid >> 1, off = (tid & 1) * 32;
    for (int kc = 0; kc < 1024; kc += 64) {
        const __half* srcA = g_ceh + (size_t)(r0 + row) * 1024 + kc + off;
        const __half* srcB = g_Wch + (size_t)row * 1024 + kc + off;
        #pragma unroll
        for (int i = 0; i < 4; ++i) {
            *(uint4*)&As[row * PADK + off + i * 8] = *(const uint4*)(srcA + i * 8);
            *(uint4*)&Bs[row * PADK + off + i * 8] = *(const uint4*)(srcB + i * 8);
        }
        __syncthreads();
        warptile_mma(smem_u32(As), smem_u32(Bs), mg, ng, lane, acc);
        __syncthreads();
    }

    #pragma unroll
    for (int mt = 0; mt < 2; ++mt) {
        int r1 = r0 + mg * 32 + mt * 16 + (lane >> 2);
        #pragma unroll
        for (int nt = 0; nt < 8; ++nt) {
            int cc = ng * 64 + nt * 8 + (lane & 3) * 2;
            *(float2*)(g_y + (size_t)r1 * 128 + cc) =
                make_float2(acc[mt][nt][0], acc[mt][nt][1]);
            *(float2*)(g_y + (size_t)(r1 + 8) * 128 + cc) =
                make_float2(acc[mt][nt][2], acc[mt][nt][3]);
        }
    }
}

// ---------------- K4: final combine + normalize + passthrough ----------------
__global__ __launch_bounds__(256) void k_final(const float* __restrict__ vars,
                                               const void* __restrict__ cvalid,
                                               const float* __restrict__ b1c,
                                               const float* __restrict__ b2c,
                                               float* __restrict__ out) {
    const unsigned FULL = 0xffffffffu;
    const int gw = (blockIdx.x * blockDim.x + threadIdx.x) >> 5;
    const int lane = threadIdx.x & 31;
    if (gw >= VN) return;
    const int mode = g_mode;

    const float* bp = (lane < 16) ? (b1c + lane * 4) : (b2c + (lane - 16) * 4);
    float4 acc = *(const float4*)bp;
    float4 yv = *(const float4*)(g_y + (size_t)gw * 128 + lane * 4);
    acc.x += yv.x; acc.y += yv.y; acc.z += yv.z; acc.w += yv.w;

    float4 lin;
    lin.x = __shfl_down_sync(FULL, acc.x, 16);
    lin.y = __shfl_down_sync(FULL, acc.y, 16);
    lin.z = __shfl_down_sync(FULL, acc.z, 16);
    lin.w = __shfl_down_sync(FULL, acc.w, 16);

    float hx = 0.f, hy = 0.f, hz = 0.f, hw = 0.f, ss = 0.f;
    if (lane < 16) {
        hx = sigf(acc.x) + lin.x;
        hy = sigf(acc.y) + lin.y;
        hz = sigf(acc.z) + lin.z;
        hw = sigf(acc.w) + lin.w;
        ss = hx * hx + hy * hy + hz * hz + hw * hw;
    }
    #pragma unroll
    for (int o = 16; o; o >>= 1) ss += __shfl_xor_sync(FULL, ss, o);
    float inv = rsqrtf(ss);

    bool cv = (lane < 16) ? read_mask(cvalid, (size_t)gw * CN + lane, mode) : false;
    bool has = __ballot_sync(FULL, cv) != 0u;

    if (lane < 16) {
        float4 o4;
        if (has) {
            o4 = make_float4(hx * inv, hy * inv, hz * inv, hw * inv);
        } else {
            o4 = *(const float4*)(vars + (size_t)gw * 64 + lane * 4);
        }
        *(float4*)(out + (size_t)gw * 64 + lane * 4) = o4;
    }
}

// ---------------- launch ----------------
extern "C" void kernel_launch(void* const* d_in, const int* in_sizes, int n_in,
                              void* d_out, int out_size) {
    const float* vars      = (const float*)d_in[0];
    const int*   lits      = (const int*)d_in[1];
    const void*  negm      = d_in[2];
    const void*  vval      = d_in[3];
    const void*  cval      = d_in[4];
    const float* Wn        = (const float*)d_in[5];
    const float* bn        = (const float*)d_in[6];
    const float* false_emb = (const float*)d_in[7];
    const float* W1v       = (const float*)d_in[8];
    const float* b1v       = (const float*)d_in[9];
    const float* W2v       = (const float*)d_in[10];
    const float* b2v       = (const float*)d_in[11];
    const float* W1c       = (const float*)d_in[12];
    const float* b1c       = (const float*)d_in[13];
    const float* W2c       = (const float*)d_in[14];
    const float* b2c       = (const float*)d_in[15];
    float* out = (float*)d_out;

    // K0: boolean encoding detection
    k_reset<<<1, 1>>>();
    const int nwords = (VN * CN * LN) / 4;
    k_scan<<<1024, 256>>>((const unsigned int*)negm, nwords);
    k_mode<<<1, 1>>>();

    // K1: weight prep + fp16 vars + P table via HMMA
    k_prep<<<1536, 64>>>(W1v, W2v, Wn, bn, false_emb);
    k_varsh<<<(AROWS * 8 + 255) / 256, 256>>>(vars, false_emb);
    k_wch<<<(128 * 1024 + 255) / 256, 256>>>(W1c, W2c);
    k_mma_P<<<dim3(129, 12), 256>>>();

    // K2: clause embeddings via fp16 gather-and-add
    k_clause<<<(VN * CN) / 32, 256>>>(lits, negm, vval, cval, b1v, b2v);

    // K3: clause combiner GEMM via HMMA
    k_gemm<<<VN / 128, 256>>>();

    // K4: final residual combine + normalize + passthrough
    k_final<<<VN / 8, 256>>>(vars, cval, b1c, b2c, out);
}